// round 15
// baseline (speedup 1.0000x reference)
#include <cuda_runtime.h>
#include <cuda_fp16.h>
#include <cstdint>

#define BQ   33
#define BBSZ 1089
#define NS   8
#define NH   8
#define NL   8
#define NCOL 512
#define MROW 272
#define HP   264
#define IMGPIX (NS*HP*HP)
#define PLN  8921088

// ---------------- scratch ----------------------------------------------------
__device__ float g_X[BBSZ * NCOL];
__device__ float g_y[MROW * NCOL];
__device__ float g_r[MROW * NCOL];
__device__ float g_z[BBSZ * NCOL];
__device__ float g_noise[BBSZ * NCOL];
__device__ float g_AtA[BBSZ * BBSZ];
__device__ uint32_t g_t1[PLN];
__device__ uint32_t g_t2[PLN];
__device__ uint4 g_wpack4[8 * 6 * 2304];
__device__ uint4 g_wpack4c[8 * 2 * 576];
__device__ uint32_t g_mA[2 * 545 * 272];
__device__ uint32_t g_mAT[2 * 136 * 1092];
__device__ uint32_t g_mQ[2 * 136 * 1092];
__device__ uint32_t g_mAtA[2 * 545 * 1092];

// ---------------- HMMA helpers ------------------------------------------------
#define HMMA16816(c, a0, a1, a2, a3, b0, b1) \
    asm volatile("mma.sync.aligned.m16n8k16.row.col.f32.f16.f16.f32 " \
        "{%0,%1,%2,%3}, {%4,%5,%6,%7}, {%8,%9}, {%0,%1,%2,%3};" \
        : "+f"((c)[0]), "+f"((c)[1]), "+f"((c)[2]), "+f"((c)[3]) \
        : "r"(a0), "r"(a1), "r"(a2), "r"(a3), "r"(b0), "r"(b1))

__device__ __forceinline__ uint32_t h2bits(__half2 h) {
    return *reinterpret_cast<uint32_t*>(&h);
}
__device__ __forceinline__ uint32_t pack2(float x, float y) {
    __half2 h = __floats2half2_rn(x, y);
    return h2bits(h);
}
__device__ __forceinline__ uint32_t pack_split(float x, float y, uint32_t& lo) {
    __half2 h = __floats2half2_rn(x, y);
    __half2 l = __floats2half2_rn(x - __low2float(h), y - __high2float(h));
    lo = h2bits(l);
    return h2bits(h);
}

// ---------------- matrix pre-pack ----------------------------------------------
__global__ void prep_mat(const float* __restrict__ src, int lds, int trans,
                         int M, int K, int Mp, uint32_t* __restrict__ dst) {
    int PS = ((K + 1) >> 1) * Mp;
    for (int e = blockIdx.x * blockDim.x + threadIdx.x; e < PS;
         e += gridDim.x * blockDim.x) {
        int m = e % Mp, kp = e / Mp;
        int k0 = 2 * kp;
        float w0 = 0.f, w1 = 0.f;
        if (m < M) {
            if (k0 < K)     w0 = trans ? src[(size_t)k0 * lds + m] : src[(size_t)m * lds + k0];
            if (k0 + 1 < K) w1 = trans ? src[(size_t)(k0 + 1) * lds + m] : src[(size_t)m * lds + k0 + 1];
        }
        uint32_t lo;
        uint32_t hi = pack_split(w0, w1, lo);
        dst[e] = hi;
        dst[PS + e] = lo;
    }
}

// ---------------- HMMA GEMM ------------------------------------------------------
template<int EPI>
__global__ void __launch_bounds__(256) hgemm(
    const uint32_t* __restrict__ Wp, int PS, int Mp,
    const float* __restrict__ X, float* __restrict__ C,
    int M, int N, int K,
    const float* __restrict__ E1, const float* __restrict__ E2,
    const float* __restrict__ stepsPtr, int stepIdx) {
    __shared__ uint2 Wsm[32 * 132];
    __shared__ uint2 Xsm[32 * 36];

    const int tid = threadIdx.x;
    const int wid = tid >> 5;
    const int lane = tid & 31;
    const int rg = lane >> 2;
    const int l3 = lane & 3;
    const int bn = blockIdx.x * 32;
    const int bm = blockIdx.y * 128;
    const int mloc = wid * 16 + rg;
    const int KpTot = (K + 1) >> 1;
    const int nCh = (KpTot + 31) >> 5;

    float acc[4][4];
#pragma unroll
    for (int nt = 0; nt < 4; nt++)
#pragma unroll
        for (int i = 0; i < 4; i++) acc[nt][i] = 0.f;

    for (int ch = 0; ch < nCh; ch++) {
        int kp0 = ch * 32;
#pragma unroll
        for (int i = 0; i < 16; i++) {
            int e = i * 256 + tid;
            int m = e & 127, kp = e >> 7;
            int kpg = kp0 + kp, gm = bm + m;
            uint32_t hi = 0, lo = 0;
            if (kpg < KpTot && gm < Mp) {
                size_t off = (size_t)kpg * Mp + gm;
                hi = Wp[off];
                lo = Wp[PS + off];
            }
            Wsm[kp * 132 + m] = make_uint2(hi, lo);
        }
#pragma unroll
        for (int i = 0; i < 4; i++) {
            int e = i * 256 + tid;
            int n = e & 31, kp = e >> 5;
            int kpg = kp0 + kp, gn = bn + n;
            float f0 = 0.f, f1 = 0.f;
            int k0 = 2 * kpg;
            if (gn < N && k0 < K) {
                f0 = X[(size_t)k0 * N + gn];
                if (k0 + 1 < K) f1 = X[(size_t)(k0 + 1) * N + gn];
            }
            uint32_t lo;
            uint32_t hi = pack_split(f0, f1, lo);
            Xsm[kp * 36 + n] = make_uint2(hi, lo);
        }
        __syncthreads();
#pragma unroll
        for (int c = 0; c < 4; c++) {
            int kl = c * 8 + l3;
            uint2 A0 = Wsm[kl * 132 + mloc];
            uint2 A1 = Wsm[kl * 132 + mloc + 8];
            uint2 A2 = Wsm[(kl + 4) * 132 + mloc];
            uint2 A3 = Wsm[(kl + 4) * 132 + mloc + 8];
#pragma unroll
            for (int nt = 0; nt < 4; nt++) {
                uint2 B0 = Xsm[kl * 36 + nt * 8 + rg];
                uint2 B1 = Xsm[(kl + 4) * 36 + nt * 8 + rg];
                HMMA16816(acc[nt], A0.x, A1.x, A2.x, A3.x, B0.x, B1.x);
                HMMA16816(acc[nt], A0.x, A1.x, A2.x, A3.x, B0.y, B1.y);
                HMMA16816(acc[nt], A0.y, A1.y, A2.y, A3.y, B0.x, B1.x);
            }
        }
        __syncthreads();
    }

    float step = (stepsPtr != nullptr) ? stepsPtr[stepIdx] : 0.f;
    int gml = bm + mloc;
#pragma unroll
    for (int nt = 0; nt < 4; nt++) {
        int gn0 = bn + nt * 8 + (l3 << 1);
#pragma unroll
        for (int half = 0; half < 2; half++) {
            int gm = gml + half * 8;
            if (gm >= M) continue;
#pragma unroll
            for (int q = 0; q < 2; q++) {
                int col = gn0 + q;
                if (col >= N) continue;
                size_t idx = (size_t)gm * N + col;
                float v = acc[nt][half * 2 + q];
                float o;
                if (EPI == 0)      o = v;
                else if (EPI == 1) o = E1[idx] - v;
                else if (EPI == 2) o = step * v + E1[idx];
                else               o = E1[idx] - step * v + E2[idx];
                C[idx] = o;
            }
        }
    }
}

// ---------------- conv weight pre-pack: uint4 fragments --------------------------
__global__ void prep_weights4(const float* __restrict__ dw2, const float* __restrict__ dw3,
                              const float* __restrict__ dw4, const float* __restrict__ bw2,
                              const float* __restrict__ bw3, const float* __restrict__ bw4,
                              uint4* __restrict__ outF, uint4* __restrict__ outC) {
    int set = blockIdx.x, n = blockIdx.y;
    const float* wt; int coutr;
    switch (set) {
        case 0: wt = dw2 + (size_t)n * 32 * 32 * 9; coutr = 32; break;
        case 1: wt = dw3 + (size_t)n * 32 * 32 * 9; coutr = 32; break;
        case 2: wt = dw4 + (size_t)n * 32 * 9;      coutr = 1;  break;
        case 3: wt = bw2 + (size_t)n * 32 * 32 * 9; coutr = 32; break;
        case 4: wt = bw3 + (size_t)n * 32 * 32 * 9; coutr = 32; break;
        case 5: wt = bw4 + (size_t)n * 32 * 9;      coutr = 1;  break;
        case 6: wt = dw4 + (size_t)n * 32 * 9;      coutr = 1;  break;
        default: wt = bw4 + (size_t)n * 32 * 9;     coutr = 1;  break;
    }
    auto wval = [&](int kp, int oc, uint32_t& hi, uint32_t& lo) {
        int k0 = 2 * kp;
        int tap = k0 >> 5, ic = k0 & 31;
        float w0 = 0.f, w1 = 0.f;
        if (oc < coutr) {
            w0 = wt[(oc * 32 + ic) * 9 + tap];
            w1 = wt[(oc * 32 + ic + 1) * 9 + tap];
        }
        hi = pack_split(w0, w1, lo);
    };
    if (set < 6) {
        uint4* o = outF + ((size_t)n * 6 + set) * 2304;
        for (int e = threadIdx.x; e < 2304; e += 256) {
            int c = e >> 7, l3 = (e >> 5) & 3, oc = e & 31;
            int kpA = c * 8 + l3;
            uint32_t hA, lA, hB, lB;
            wval(kpA, oc, hA, lA);
            wval(kpA + 4, oc, hB, lB);
            o[e] = make_uint4(hA, hB, lA, lB);
        }
    } else {
        uint4* o = outC + ((size_t)n * 2 + (set - 6)) * 576;
        for (int e = threadIdx.x; e < 576; e += 256) {
            int c = e >> 5, l3 = (e >> 3) & 3, oc = e & 7;
            int kpA = c * 8 + l3;
            uint32_t hA, lA, hB, lB;
            wval(kpA, oc, hA, lA);
            wval(kpA + 4, oc, hB, lB);
            o[e] = make_uint4(hA, hB, lA, lB);
        }
    }
}

__device__ __forceinline__ int ximg_idx(int s, int gy, int gx) {
    int h = gy / 33, i = gy % 33, l = gx / 33, j = gx % 33;
    return (i * 33 + j) * NCOL + l * (NH * NS) + h * NS + s;
}

#define WSF_BYTES (72 * 34 * 16)   // 39168
#define WSC_BYTES (72 * 10 * 16)   // 11520
__device__ __forceinline__ void load_w4(const uint4* __restrict__ wp,
                                        uint4* __restrict__ ws, int tid) {
#pragma unroll
    for (int i = 0; i < 9; i++) {
        int e = i * 256 + tid;
        ws[(e >> 5) * 34 + (e & 31)] = wp[e];
    }
}
__device__ __forceinline__ void load_w4c(const uint4* __restrict__ wp,
                                         uint4* __restrict__ ws, int tid) {
#pragma unroll
    for (int i = 0; i < 3; i++) {
        int e = i * 256 + tid;
        if (e < 576) ws[(e >> 3) * 10 + (e & 7)] = wp[e];
    }
}

// wide tile constants
#define WP0 408
#define WP1 344
#define WNP0 (11 * 35)
#define WNP1 (34 * 10)

// ============ WIDE fused conv1+conv2 (2 x 256 px / block) ========================
template<int MODE>
__global__ void __launch_bounds__(256)
conv12_hmma(const float* __restrict__ xin,
            const float* __restrict__ w1g,
            const float* __restrict__ b1g,
            const uint4* __restrict__ wpack,
            const float* __restrict__ bias2,
            uint32_t* __restrict__ out) {
    extern __shared__ char smem[];
    constexpr int PSTR = (MODE == 0) ? WP0 : WP1;
    constexpr int WROW = (MODE == 0) ? 35 : 10;
    constexpr int NPOS = (MODE == 0) ? WNP0 : WNP1;
    constexpr int RW   = (MODE == 0) ? 37 : 12;
    constexpr int RAWN = (MODE == 0) ? 13 * 37 : 36 * 12;
    uint4* ws = (uint4*)smem;
    uint32_t* hhi = (uint32_t*)(smem + WSF_BYTES);
    float* raw = (float*)(smem + WSF_BYTES + 16 * PSTR * 4);
    float* w1s = raw + ((RAWN + 3) & ~3);

    const int tid = threadIdx.x;
    const int wid = tid >> 5;
    const int lane = tid & 31;
    const int rg = lane >> 2;
    const int l3 = lane & 3;
    const int kq = l3 * 2;

    int n_img, tp = 0, txb = 0;
    if (MODE == 0) {
        n_img = blockIdx.x / 3;
        tp = blockIdx.x % 3;          // tile pair: tiles 2tp, 2tp+1 (of 5)
    } else {
        int b = blockIdx.x;
        txb = b % 33; b /= 33;
        tp = b % 5;                    // ty pair: ty = 2tp, 2tp+1 (of 9)
        n_img = b / 5;
    }

    load_w4(wpack, ws, tid);
    for (int e = tid; e < 320; e += 256)
        w1s[e] = (e < 288) ? w1g[e] : b1g[e - 288];

    for (int sub = 0; sub < 2; sub++) {
        int tile = 2 * tp + sub;
        bool active = (MODE == 0) ? (tile < 5) : (tile < 9);
        int p0 = 0, y_first = 0, y0t = 0, x0t = 0;
        if (MODE == 0) { p0 = tile * 256; y_first = p0 / 33; }
        else           { y0t = tile * 32; x0t = txb * 8; }

        __syncthreads();   // previous tile's MMA smem reads done
        if (active) {
            if (MODE == 0) {
                for (int e = tid; e < RAWN; e += 256) {
                    int ry = e / RW, rx = e % RW;
                    int gy = y_first - 2 + ry, gx = rx - 2;
                    bool ok = (gy >= 0) && (gy < 33) && (gx >= 0) && (gx < 33);
                    raw[e] = ok ? xin[(gy * 33 + gx) * NCOL + n_img] : 0.f;
                }
            } else {
                for (int e = tid; e < RAWN; e += 256) {
                    int ry = e / RW, rx = e % RW;
                    int gy = y0t - 2 + ry, gx = x0t - 2 + rx;
                    bool ok = (gy >= 0) && (gy < HP) && (gx >= 0) && (gx < HP);
                    raw[e] = ok ? xin[ximg_idx(n_img, gy, gx)] : 0.f;
                }
            }
        }
        __syncthreads();
        if (active) {
            for (int q = tid; q < NPOS; q += 256) {
                int hy = q / WROW, hx = q % WROW;
                int gy, gx, GH, GW;
                if (MODE == 0) { gy = y_first - 1 + hy; gx = hx - 1; GH = 33; GW = 33; }
                else           { gy = y0t - 1 + hy;     gx = x0t - 1 + hx; GH = HP; GW = HP; }
                bool valid = (gy >= 0) && (gy < GH) && (gx >= 0) && (gx < GW);
                float c1[32];
                if (valid) {
                    float t0 = raw[hy * RW + hx],     t1 = raw[hy * RW + hx + 1],     t2 = raw[hy * RW + hx + 2];
                    float t3 = raw[(hy+1) * RW + hx], t4 = raw[(hy+1) * RW + hx + 1], t5 = raw[(hy+1) * RW + hx + 2];
                    float t6 = raw[(hy+2) * RW + hx], t7 = raw[(hy+2) * RW + hx + 1], t8 = raw[(hy+2) * RW + hx + 2];
#pragma unroll
                    for (int oc = 0; oc < 32; oc++) {
                        const float* w = w1s + oc * 9;
                        float s = w1s[288 + oc];
                        s += t0*w[0] + t1*w[1] + t2*w[2]
                           + t3*w[3] + t4*w[4] + t5*w[5]
                           + t6*w[6] + t7*w[7] + t8*w[8];
                        c1[oc] = fmaxf(s, 0.f);
                    }
                } else {
#pragma unroll
                    for (int oc = 0; oc < 32; oc++) c1[oc] = 0.f;
                }
#pragma unroll
                for (int p = 0; p < 16; p++)
                    hhi[p * PSTR + q] = pack2(c1[2*p], c1[2*p+1]);
            }
        }
        __syncthreads();
        if (!active) continue;

        const int m0 = wid * 16 + rg;
        int base[4];
#pragma unroll
        for (int q = 0; q < 4; q++) {
            int m = m0 + (q & 1) * 8 + (q >> 1) * 128;
            if (MODE == 0) {
                int p = p0 + m;
                int yl = p / 33;
                base[q] = (p < BBSZ) ? (yl - y_first) * 35 + (p - yl * 33) : 0;
            } else {
                base[q] = (m >> 3) * 10 + (m & 7);
            }
        }
        const uint32_t* ph = hhi + l3 * PSTR;

        float acc[2][4][4];
#pragma unroll
        for (int tt = 0; tt < 2; tt++)
#pragma unroll
            for (int nt = 0; nt < 4; nt++)
#pragma unroll
                for (int i = 0; i < 4; i++) acc[tt][nt][i] = 0.f;

#pragma unroll
        for (int t = 0; t < 9; t++) {
            const int toff = (t / 3) * WROW + (t % 3);
#pragma unroll
            for (int e2 = 0; e2 < 2; e2++) {
                const int c = 2 * t + e2;
                const int pb = e2 * 8 * PSTR + toff;
                uint32_t a0 = ph[base[0] + pb];
                uint32_t a1 = ph[base[1] + pb];
                uint32_t a2 = ph[base[0] + pb + 4 * PSTR];
                uint32_t a3 = ph[base[1] + pb + 4 * PSTR];
                uint32_t a4 = ph[base[2] + pb];
                uint32_t a5 = ph[base[3] + pb];
                uint32_t a6 = ph[base[2] + pb + 4 * PSTR];
                uint32_t a7 = ph[base[3] + pb + 4 * PSTR];
                const int row = (c * 4 + l3) * 34 + rg;
#pragma unroll
                for (int nt = 0; nt < 4; nt++) {
                    uint4 B = ws[row + nt * 8];
                    HMMA16816(acc[0][nt], a0, a1, a2, a3, B.x, B.y);
                    HMMA16816(acc[0][nt], a0, a1, a2, a3, B.z, B.w);
                    HMMA16816(acc[1][nt], a4, a5, a6, a7, B.x, B.y);
                    HMMA16816(acc[1][nt], a4, a5, a6, a7, B.z, B.w);
                }
            }
        }

#pragma unroll
        for (int tt = 0; tt < 2; tt++) {
#pragma unroll
            for (int nt = 0; nt < 4; nt++) {
                int oc = nt * 8 + kq;
                int p2 = nt * 4 + l3;
                float b0 = bias2[oc], b1 = bias2[oc + 1];
                uint32_t h0 = pack2(fmaxf(acc[tt][nt][0] + b0, 0.f), fmaxf(acc[tt][nt][1] + b1, 0.f));
                uint32_t h1 = pack2(fmaxf(acc[tt][nt][2] + b0, 0.f), fmaxf(acc[tt][nt][3] + b1, 0.f));
                int m = m0 + tt * 128;
                if (MODE == 0) {
                    int pl = p0 + m, phh = pl + 8;
                    if (pl < BBSZ) out[(size_t)(n_img * 16 + p2) * BBSZ + pl] = h0;
                    if (phh < BBSZ) out[(size_t)(n_img * 16 + p2) * BBSZ + phh] = h1;
                } else {
                    int oyl = y0t + (m >> 3), oxl = x0t + (m & 7);
                    int oyh = y0t + ((m + 8) >> 3), oxh = x0t + ((m + 8) & 7);
                    if (oyl < HP) out[((size_t)(n_img * 16 + p2) * HP + oyl) * HP + oxl] = h0;
                    if (oyh < HP) out[((size_t)(n_img * 16 + p2) * HP + oyh) * HP + oxh] = h1;
                }
            }
        }
    }
}

// ============ WIDE mid conv (2 x 256 px / block, 32 oc) ==========================
template<int MODE>
__global__ void __launch_bounds__(256)
conv_hmma_w(const uint32_t* __restrict__ in,
            const uint4* __restrict__ wpack,
            const float* __restrict__ bias,
            uint32_t* __restrict__ out) {
    extern __shared__ char smem[];
    constexpr int PSTR = (MODE == 0) ? WP0 : WP1;
    constexpr int WROW = (MODE == 0) ? 35 : 10;
    constexpr int NPOS = (MODE == 0) ? WNP0 : WNP1;
    uint4* ws = (uint4*)smem;
    uint32_t* hhi = (uint32_t*)(smem + WSF_BYTES);

    const int tid = threadIdx.x;
    const int wid = tid >> 5;
    const int lane = tid & 31;
    const int rg = lane >> 2;
    const int l3 = lane & 3;
    const int kq = l3 * 2;

    int n_img, tp = 0, txb = 0;
    if (MODE == 0) {
        n_img = blockIdx.x / 3;
        tp = blockIdx.x % 3;
    } else {
        int b = blockIdx.x;
        txb = b % 33; b /= 33;
        tp = b % 5;
        n_img = b / 5;
    }

    load_w4(wpack, ws, tid);

    for (int sub = 0; sub < 2; sub++) {
        int tile = 2 * tp + sub;
        bool active = (MODE == 0) ? (tile < 5) : (tile < 9);
        int p0 = 0, y_first = 0, y0t = 0, x0t = 0;
        if (MODE == 0) { p0 = tile * 256; y_first = p0 / 33; }
        else           { y0t = tile * 32; x0t = txb * 8; }

        __syncthreads();
        if (active) {
            if (MODE == 0) {
                for (int e = tid; e < 16 * NPOS; e += 256) {
                    int pair = e / NPOS, pos = e % NPOS;
                    int row = pos / 35, xp = pos % 35;
                    int gy = y_first - 1 + row, gx = xp - 1;
                    bool ok = (gy >= 0) && (gy < 33) && (xp >= 1) && (xp < 34);
                    hhi[pair * PSTR + pos] =
                        ok ? in[(size_t)(n_img * 16 + pair) * BBSZ + gy * 33 + gx] : 0u;
                }
            } else {
                for (int e = tid; e < 16 * NPOS; e += 256) {
                    int pair = e / NPOS, pos = e % NPOS;
                    int row = pos / 10, xp = pos % 10;
                    int gy = y0t - 1 + row, gx = x0t - 1 + xp;
                    bool ok = (gy >= 0) && (gy < HP) && (gx >= 0) && (gx < HP);
                    hhi[pair * PSTR + pos] =
                        ok ? in[((size_t)(n_img * 16 + pair) * HP + gy) * HP + gx] : 0u;
                }
            }
        }
        __syncthreads();
        if (!active) continue;

        const int m0 = wid * 16 + rg;
        int base[4];
#pragma unroll
        for (int q = 0; q < 4; q++) {
            int m = m0 + (q & 1) * 8 + (q >> 1) * 128;
            if (MODE == 0) {
                int p = p0 + m;
                int yl = p / 33;
                base[q] = (p < BBSZ) ? (yl - y_first) * 35 + (p - yl * 33) : 0;
            } else {
                base[q] = (m >> 3) * 10 + (m & 7);
            }
        }
        const uint32_t* ph = hhi + l3 * PSTR;

        float acc[2][4][4];
#pragma unroll
        for (int tt = 0; tt < 2; tt++)
#pragma unroll
            for (int nt = 0; nt < 4; nt++)
#pragma unroll
                for (int i = 0; i < 4; i++) acc[tt][nt][i] = 0.f;

#pragma unroll
        for (int t = 0; t < 9; t++) {
            const int toff = (t / 3) * WROW + (t % 3);
#pragma unroll
            for (int e2 = 0; e2 < 2; e2++) {
                const int c = 2 * t + e2;
                const int pb = e2 * 8 * PSTR + toff;
                uint32_t a0 = ph[base[0] + pb];
                uint32_t a1 = ph[base[1] + pb];
                uint32_t a2 = ph[base[0] + pb + 4 * PSTR];
                uint32_t a3 = ph[base[1] + pb + 4 * PSTR];
                uint32_t a4 = ph[base[2] + pb];
                uint32_t a5 = ph[base[3] + pb];
                uint32_t a6 = ph[base[2] + pb + 4 * PSTR];
                uint32_t a7 = ph[base[3] + pb + 4 * PSTR];
                const int row = (c * 4 + l3) * 34 + rg;
#pragma unroll
                for (int nt = 0; nt < 4; nt++) {
                    uint4 B = ws[row + nt * 8];
                    HMMA16816(acc[0][nt], a0, a1, a2, a3, B.x, B.y);
                    HMMA16816(acc[0][nt], a0, a1, a2, a3, B.z, B.w);
                    HMMA16816(acc[1][nt], a4, a5, a6, a7, B.x, B.y);
                    HMMA16816(acc[1][nt], a4, a5, a6, a7, B.z, B.w);
                }
            }
        }

#pragma unroll
        for (int tt = 0; tt < 2; tt++) {
#pragma unroll
            for (int nt = 0; nt < 4; nt++) {
                int oc = nt * 8 + kq;
                int p2 = nt * 4 + l3;
                float b0 = bias[oc], b1 = bias[oc + 1];
                uint32_t h0 = pack2(fmaxf(acc[tt][nt][0] + b0, 0.f), fmaxf(acc[tt][nt][1] + b1, 0.f));
                uint32_t h1 = pack2(fmaxf(acc[tt][nt][2] + b0, 0.f), fmaxf(acc[tt][nt][3] + b1, 0.f));
                int m = m0 + tt * 128;
                if (MODE == 0) {
                    int pl = p0 + m, phh = pl + 8;
                    if (pl < BBSZ) out[(size_t)(n_img * 16 + p2) * BBSZ + pl] = h0;
                    if (phh < BBSZ) out[(size_t)(n_img * 16 + p2) * BBSZ + phh] = h1;
                } else {
                    int oyl = y0t + (m >> 3), oxl = x0t + (m & 7);
                    int oyh = y0t + ((m + 8) >> 3), oxh = x0t + ((m + 8) & 7);
                    if (oyl < HP) out[((size_t)(n_img * 16 + p2) * HP + oyl) * HP + oxl] = h0;
                    if (oyh < HP) out[((size_t)(n_img * 16 + p2) * HP + oyh) * HP + oxh] = h1;
                }
            }
        }
    }
}

// ---------------- NARROW conv4 (128 px, 1 oc) ------------------------------------
template<int MODE, int OUTM>
__global__ void __launch_bounds__(256)
conv_hmma_n(const uint32_t* __restrict__ in,
            const uint4* __restrict__ wpack,
            float* __restrict__ out) {
    extern __shared__ char smem[];
    uint4* ws = (uint4*)smem;
    constexpr int PSTR = (MODE == 0) ? 248 : 184;
    constexpr int WROW = (MODE == 0) ? 35 : 10;
    constexpr int NPOS = (MODE == 0) ? 245 : 180;
    uint32_t* hhi = (uint32_t*)(smem + WSC_BYTES);

    const int tid = threadIdx.x;
    const int wid = tid >> 5;
    const int lane = tid & 31;
    const int rg = lane >> 2;
    const int l3 = lane & 3;

    int n_img, p0 = 0, y_first = 0, y0t = 0, x0t = 0;
    if (MODE == 0) {
        n_img = blockIdx.x / 9;
        p0 = (blockIdx.x % 9) * 128;
        y_first = p0 / 33;
    } else {
        int b = blockIdx.x;
        int tx = b % 33; b /= 33;
        int ty = b % 17; b /= 17;
        n_img = b; y0t = ty * 16; x0t = tx * 8;
    }

    load_w4c(wpack, ws, tid);

    if (MODE == 0) {
        for (int e = tid; e < 16 * NPOS; e += 256) {
            int pair = e / NPOS, pos = e % NPOS;
            int row = pos / 35, xp = pos % 35;
            int gy = y_first - 1 + row, gx = xp - 1;
            bool ok = (gy >= 0) && (gy < 33) && (xp >= 1) && (xp < 34);
            hhi[pair * PSTR + pos] =
                ok ? in[(size_t)(n_img * 16 + pair) * BBSZ + gy * 33 + gx] : 0u;
        }
    } else {
        for (int e = tid; e < 16 * NPOS; e += 256) {
            int pair = e / NPOS, pos = e % NPOS;
            int row = pos / 10, xp = pos % 10;
            int gy = y0t - 1 + row, gx = x0t - 1 + xp;
            bool ok = (gy >= 0) && (gy < HP) && (gx >= 0) && (gx < HP);
            hhi[pair * PSTR + pos] =
                ok ? in[((size_t)(n_img * 16 + pair) * HP + gy) * HP + gx] : 0u;
        }
    }
    __syncthreads();

    int m_lo = wid * 16 + rg;
    int m_hi = m_lo + 8;
    int base_lo, base_hi;
    if (MODE == 0) {
        int pl = p0 + m_lo, ph = p0 + m_hi;
        int yl = pl / 33, yh = ph / 33;
        base_lo = (pl < BBSZ) ? (yl - y_first) * 35 + (pl - yl * 33) : 0;
        base_hi = (ph < BBSZ) ? (yh - y_first) * 35 + (ph - yh * 33) : 0;
    } else {
        base_lo = (m_lo >> 3) * 10 + (m_lo & 7);
        base_hi = (m_hi >> 3) * 10 + (m_hi & 7);
    }
    const uint32_t* phi_lo = hhi + l3 * PSTR + base_lo;
    const uint32_t* phi_hi = hhi + l3 * PSTR + base_hi;

    float acc[4];
#pragma unroll
    for (int i = 0; i < 4; i++) acc[i] = 0.f;

#pragma unroll
    for (int t = 0; t < 9; t++) {
        const int toff = (t / 3) * WROW + (t % 3);
#pragma unroll
        for (int e2 = 0; e2 < 2; e2++) {
            const int c = 2 * t + e2;
            const int pb = e2 * 8 * PSTR + toff;
            uint32_t a0h = phi_lo[pb];
            uint32_t a1h = phi_hi[pb];
            uint32_t a2h = phi_lo[pb + 4 * PSTR];
            uint32_t a3h = phi_hi[pb + 4 * PSTR];
            uint4 B = ws[(c * 4 + l3) * 10 + rg];
            HMMA16816(acc, a0h, a1h, a2h, a3h, B.x, B.y);
            HMMA16816(acc, a0h, a1h, a2h, a3h, B.z, B.w);
        }
    }

    if (OUTM == 1) {
        if (l3 == 0) {
            int pl = p0 + m_lo, ph = p0 + m_hi;
            if (pl < BBSZ) out[(size_t)pl * NCOL + n_img] = acc[0];
            if (ph < BBSZ) out[(size_t)ph * NCOL + n_img] = acc[2];
        }
    } else {
        if (l3 == 0) {
            int gyl = y0t + (m_lo >> 3), gxl = x0t + (m_lo & 7);
            int gyh = y0t + (m_hi >> 3), gxh = x0t + (m_hi & 7);
            if (gyl < HP) { int ix = ximg_idx(n_img, gyl, gxl); out[ix] -= acc[0]; }
            if (gyh < HP) { int ix = ximg_idx(n_img, gyh, gxh); out[ix] -= acc[2]; }
        }
    }
}

// ---------------- blockify / unblockify ------------------------------------------
__global__ void blockify_input_kernel(const float* __restrict__ in, float* __restrict__ Xb) {
    int idx = blockIdx.x * blockDim.x + threadIdx.x;
    if (idx >= BBSZ * NCOL) return;
    int r = idx / NCOL, n = idx % NCOL;
    int i = r / BQ, j = r % BQ;
    int l = n / (NH * NS), h = (n / NS) % NH, s = n % NS;
    Xb[idx] = in[(s * HP + h * BQ + i) * HP + l * BQ + j];
}
__global__ void unblockify_kernel(const float* __restrict__ X, float* __restrict__ img) {
    int idx = blockIdx.x * blockDim.x + threadIdx.x;
    if (idx >= IMGPIX) return;
    int s = idx / (HP * HP);
    int rem = idx % (HP * HP);
    int R = rem / HP, C = rem % HP;
    int h = R / BQ, i = R % BQ, l = C / BQ, j = C % BQ;
    img[idx] = X[(i * BQ + j) * NCOL + (l * (NH * NS) + h * NS + s)];
}

// ---------------- host driver ------------------------------------------------------
extern "C" void kernel_launch(void* const* d_in, const int* in_sizes, int n_in,
                              void* d_out, int out_size) {
    const float* inputs = (const float*)d_in[0];
    const float* A      = (const float*)d_in[1];
    const float* Q      = (const float*)d_in[2];
    const float* steps  = (const float*)d_in[3];
    const float* den_w1 = (const float*)d_in[4];
    const float* den_b1 = (const float*)d_in[5];
    const float* den_w2 = (const float*)d_in[6];
    const float* den_b2 = (const float*)d_in[7];
    const float* den_w3 = (const float*)d_in[8];
    const float* den_b3 = (const float*)d_in[9];
    const float* den_w4 = (const float*)d_in[10];
    const float* deb_w1 = (const float*)d_in[11];
    const float* deb_b1 = (const float*)d_in[12];
    const float* deb_w2 = (const float*)d_in[13];
    const float* deb_b2 = (const float*)d_in[14];
    const float* deb_w3 = (const float*)d_in[15];
    const float* deb_b3 = (const float*)d_in[16];
    const float* deb_w4 = (const float*)d_in[17];
    int layers = in_sizes[3];

    float *pX, *pY, *pR, *pZ, *pN, *pAtA;
    uint32_t *pT1, *pT2, *pmA, *pmAT, *pmQ, *pmAtA;
    uint4 *pW4, *pW4c;
    cudaGetSymbolAddress((void**)&pX, g_X);
    cudaGetSymbolAddress((void**)&pY, g_y);
    cudaGetSymbolAddress((void**)&pR, g_r);
    cudaGetSymbolAddress((void**)&pZ, g_z);
    cudaGetSymbolAddress((void**)&pN, g_noise);
    cudaGetSymbolAddress((void**)&pAtA, g_AtA);
    cudaGetSymbolAddress((void**)&pT1, g_t1);
    cudaGetSymbolAddress((void**)&pT2, g_t2);
    cudaGetSymbolAddress((void**)&pW4, g_wpack4);
    cudaGetSymbolAddress((void**)&pW4c, g_wpack4c);
    cudaGetSymbolAddress((void**)&pmA, g_mA);
    cudaGetSymbolAddress((void**)&pmAT, g_mAT);
    cudaGetSymbolAddress((void**)&pmQ, g_mQ);
    cudaGetSymbolAddress((void**)&pmAtA, g_mAtA);

    const int EW = 256;
    const int EG = (IMGPIX + EW - 1) / EW;

    const int SM0W = WSF_BYTES + 16 * WP0 * 4;
    const int SM1W = WSF_BYTES + 16 * WP1 * 4;
    const int SM0C = WSC_BYTES + 16 * 248 * 4;
    const int SM1C = WSC_BYTES + 16 * 184 * 4;
    const int SM12_0 = SM0W + ((13 * 37 + 3) & ~3) * 4 + 320 * 4;
    const int SM12_1 = SM1W + ((36 * 12 + 3) & ~3) * 4 + 320 * 4;
    cudaFuncSetAttribute(conv12_hmma<0>, cudaFuncAttributeMaxDynamicSharedMemorySize, SM12_0);
    cudaFuncSetAttribute(conv12_hmma<1>, cudaFuncAttributeMaxDynamicSharedMemorySize, SM12_1);
    cudaFuncSetAttribute(conv_hmma_w<0>, cudaFuncAttributeMaxDynamicSharedMemorySize, SM0W);
    cudaFuncSetAttribute(conv_hmma_w<1>, cudaFuncAttributeMaxDynamicSharedMemorySize, SM1W);
    cudaFuncSetAttribute(conv_hmma_n<0,1>, cudaFuncAttributeMaxDynamicSharedMemorySize, SM0C);
    cudaFuncSetAttribute(conv_hmma_n<1,3>, cudaFuncAttributeMaxDynamicSharedMemorySize, SM1C);

    const int G0W = NCOL * 3;        // 1536 (2 tiles each, 5 tiles/img)
    const int G1W = 8 * 5 * 33;      // 1320 (2 ty each, 9 rows/img)
    const int G0 = NCOL * 9;
    const int G1 = 8 * 17 * 33;

    const int PS_A   = 545 * 272;
    const int PS_ATQ = 136 * 1092;
    const int PS_AtA = 545 * 1092;

    prep_weights4<<<dim3(8, layers), 256>>>(den_w2, den_w3, den_w4,
                                            deb_w2, deb_w3, deb_w4, pW4, pW4c);
    blockify_input_kernel<<<EG, EW>>>(inputs, pZ);
    prep_mat<<<580, 256>>>(A, 1089, 0, 272, 1089, 272, pmA);
    prep_mat<<<580, 256>>>(A, 1089, 1, 1089, 272, 1092, pmAT);
    prep_mat<<<580, 256>>>(Q, 272, 0, 1089, 272, 1092, pmQ);
    hgemm<0><<<dim3(16, 3), 256>>>(pmA, PS_A, 272, pZ, pY, 272, 512, 1089,
                                   nullptr, nullptr, nullptr, 0);
    hgemm<0><<<dim3(16, 9), 256>>>(pmQ, PS_ATQ, 1092, pY, pX, 1089, 512, 272,
                                   nullptr, nullptr, nullptr, 0);
    hgemm<0><<<dim3(35, 9), 256>>>(pmAT, PS_ATQ, 1092, A, pAtA, 1089, 1089, 272,
                                   nullptr, nullptr, nullptr, 0);
    prep_mat<<<2325, 256>>>(pAtA, 1089, 0, 1089, 1089, 1092, pmAtA);

    for (int n = 0; n < layers; n++) {
        const uint4* wf = pW4 + (size_t)(n * 6) * 2304;
        const uint4* wc = pW4c + (size_t)(n * 2) * 576;
        hgemm<1><<<dim3(16, 3), 256>>>(pmA, PS_A, 272, pX, pR, 272, 512, 1089,
                                       pY, nullptr, nullptr, 0);
        hgemm<2><<<dim3(16, 9), 256>>>(pmAT, PS_ATQ, 1092, pR, pZ, 1089, 512, 272,
                                       pX, nullptr, steps, n);
        conv12_hmma<0><<<G0W, 256, SM12_0>>>(pX, den_w1 + (size_t)n * 32 * 9,
                                             den_b1 + n * 32, wf + 0 * 2304,
                                             den_b2 + n * 32, pT1);
        conv_hmma_w<0><<<G0W, 256, SM0W>>>(pT1, wf + 1 * 2304, den_b3 + n * 32, pT2);
        conv_hmma_n<0,1><<<G0, 256, SM0C>>>(pT2, wc + 0 * 576, pN);
        hgemm<3><<<dim3(16, 9), 256>>>(pmAtA, PS_AtA, 1092, pN, pX, 1089, 512, 1089,
                                       pZ, pN, steps, n);
        conv12_hmma<1><<<G1W, 256, SM12_1>>>(pX, deb_w1 + (size_t)n * 32 * 9,
                                             deb_b1 + n * 32, wf + 3 * 2304,
                                             deb_b2 + n * 32, pT1);
        conv_hmma_w<1><<<G1W, 256, SM1W>>>(pT1, wf + 4 * 2304, deb_b3 + n * 32, pT2);
        conv_hmma_n<1,3><<<G1, 256, SM1C>>>(pT2, wc + 1 * 576, pX);
    }

    unblockify_kernel<<<EG, EW>>>(pX, (float*)d_out);
}

// round 16
// speedup vs baseline: 1.0810x; 1.0810x over previous
#include <cuda_runtime.h>
#include <cuda_fp16.h>
#include <cstdint>

#define BQ   33
#define BBSZ 1089
#define NS   8
#define NH   8
#define NL   8
#define NCOL 512
#define MROW 272
#define HP   264
#define IMGPIX (NS*HP*HP)
#define PLN  8921088

// ---------------- scratch ----------------------------------------------------
__device__ float g_X[BBSZ * NCOL];
__device__ float g_y[MROW * NCOL];
__device__ float g_r[MROW * NCOL];
__device__ float g_z[BBSZ * NCOL];
__device__ float g_noise[BBSZ * NCOL];
__device__ float g_AtA[BBSZ * BBSZ];
__device__ uint32_t g_t1[PLN];
__device__ uint32_t g_t2[PLN];
__device__ uint4 g_wpack4[8 * 6 * 2304];
__device__ uint4 g_wpack4c[8 * 2 * 576];
__device__ uint32_t g_mA[2 * 545 * 272];
__device__ uint32_t g_mAT[2 * 136 * 1092];
__device__ uint32_t g_mQ[2 * 136 * 1092];
__device__ uint32_t g_mAtA[2 * 545 * 1092];

// ---------------- HMMA helpers ------------------------------------------------
#define HMMA16816(c, a0, a1, a2, a3, b0, b1) \
    asm volatile("mma.sync.aligned.m16n8k16.row.col.f32.f16.f16.f32 " \
        "{%0,%1,%2,%3}, {%4,%5,%6,%7}, {%8,%9}, {%0,%1,%2,%3};" \
        : "+f"((c)[0]), "+f"((c)[1]), "+f"((c)[2]), "+f"((c)[3]) \
        : "r"(a0), "r"(a1), "r"(a2), "r"(a3), "r"(b0), "r"(b1))

__device__ __forceinline__ uint32_t h2bits(__half2 h) {
    return *reinterpret_cast<uint32_t*>(&h);
}
__device__ __forceinline__ uint32_t pack2(float x, float y) {
    __half2 h = __floats2half2_rn(x, y);
    return h2bits(h);
}
__device__ __forceinline__ uint32_t pack_split(float x, float y, uint32_t& lo) {
    __half2 h = __floats2half2_rn(x, y);
    __half2 l = __floats2half2_rn(x - __low2float(h), y - __high2float(h));
    lo = h2bits(l);
    return h2bits(h);
}

// ---------------- matrix pre-pack ----------------------------------------------
__global__ void prep_mat(const float* __restrict__ src, int lds, int trans,
                         int M, int K, int Mp, uint32_t* __restrict__ dst) {
    int PS = ((K + 1) >> 1) * Mp;
    for (int e = blockIdx.x * blockDim.x + threadIdx.x; e < PS;
         e += gridDim.x * blockDim.x) {
        int m = e % Mp, kp = e / Mp;
        int k0 = 2 * kp;
        float w0 = 0.f, w1 = 0.f;
        if (m < M) {
            if (k0 < K)     w0 = trans ? src[(size_t)k0 * lds + m] : src[(size_t)m * lds + k0];
            if (k0 + 1 < K) w1 = trans ? src[(size_t)(k0 + 1) * lds + m] : src[(size_t)m * lds + k0 + 1];
        }
        uint32_t lo;
        uint32_t hi = pack_split(w0, w1, lo);
        dst[e] = hi;
        dst[PS + e] = lo;
    }
}

// ---------------- HMMA GEMM ------------------------------------------------------
template<int EPI>
__global__ void __launch_bounds__(256) hgemm(
    const uint32_t* __restrict__ Wp, int PS, int Mp,
    const float* __restrict__ X, float* __restrict__ C,
    int M, int N, int K,
    const float* __restrict__ E1, const float* __restrict__ E2,
    const float* __restrict__ stepsPtr, int stepIdx) {
    __shared__ uint2 Wsm[32 * 132];
    __shared__ uint2 Xsm[32 * 36];

    const int tid = threadIdx.x;
    const int wid = tid >> 5;
    const int lane = tid & 31;
    const int rg = lane >> 2;
    const int l3 = lane & 3;
    const int bn = blockIdx.x * 32;
    const int bm = blockIdx.y * 128;
    const int mloc = wid * 16 + rg;
    const int KpTot = (K + 1) >> 1;
    const int nCh = (KpTot + 31) >> 5;

    float acc[4][4];
#pragma unroll
    for (int nt = 0; nt < 4; nt++)
#pragma unroll
        for (int i = 0; i < 4; i++) acc[nt][i] = 0.f;

    for (int ch = 0; ch < nCh; ch++) {
        int kp0 = ch * 32;
#pragma unroll
        for (int i = 0; i < 16; i++) {
            int e = i * 256 + tid;
            int m = e & 127, kp = e >> 7;
            int kpg = kp0 + kp, gm = bm + m;
            uint32_t hi = 0, lo = 0;
            if (kpg < KpTot && gm < Mp) {
                size_t off = (size_t)kpg * Mp + gm;
                hi = Wp[off];
                lo = Wp[PS + off];
            }
            Wsm[kp * 132 + m] = make_uint2(hi, lo);
        }
#pragma unroll
        for (int i = 0; i < 4; i++) {
            int e = i * 256 + tid;
            int n = e & 31, kp = e >> 5;
            int kpg = kp0 + kp, gn = bn + n;
            float f0 = 0.f, f1 = 0.f;
            int k0 = 2 * kpg;
            if (gn < N && k0 < K) {
                f0 = X[(size_t)k0 * N + gn];
                if (k0 + 1 < K) f1 = X[(size_t)(k0 + 1) * N + gn];
            }
            uint32_t lo;
            uint32_t hi = pack_split(f0, f1, lo);
            Xsm[kp * 36 + n] = make_uint2(hi, lo);
        }
        __syncthreads();
#pragma unroll
        for (int c = 0; c < 4; c++) {
            int kl = c * 8 + l3;
            uint2 A0 = Wsm[kl * 132 + mloc];
            uint2 A1 = Wsm[kl * 132 + mloc + 8];
            uint2 A2 = Wsm[(kl + 4) * 132 + mloc];
            uint2 A3 = Wsm[(kl + 4) * 132 + mloc + 8];
#pragma unroll
            for (int nt = 0; nt < 4; nt++) {
                uint2 B0 = Xsm[kl * 36 + nt * 8 + rg];
                uint2 B1 = Xsm[(kl + 4) * 36 + nt * 8 + rg];
                HMMA16816(acc[nt], A0.x, A1.x, A2.x, A3.x, B0.x, B1.x);
                HMMA16816(acc[nt], A0.x, A1.x, A2.x, A3.x, B0.y, B1.y);
                HMMA16816(acc[nt], A0.y, A1.y, A2.y, A3.y, B0.x, B1.x);
            }
        }
        __syncthreads();
    }

    float step = (stepsPtr != nullptr) ? stepsPtr[stepIdx] : 0.f;
    int gml = bm + mloc;
#pragma unroll
    for (int nt = 0; nt < 4; nt++) {
        int gn0 = bn + nt * 8 + (l3 << 1);
#pragma unroll
        for (int half = 0; half < 2; half++) {
            int gm = gml + half * 8;
            if (gm >= M) continue;
#pragma unroll
            for (int q = 0; q < 2; q++) {
                int col = gn0 + q;
                if (col >= N) continue;
                size_t idx = (size_t)gm * N + col;
                float v = acc[nt][half * 2 + q];
                float o;
                if (EPI == 0)      o = v;
                else if (EPI == 1) o = E1[idx] - v;
                else if (EPI == 2) o = step * v + E1[idx];
                else               o = E1[idx] - step * v + E2[idx];
                C[idx] = o;
            }
        }
    }
}

// ---------------- conv weight pre-pack: uint4 fragments --------------------------
__global__ void prep_weights4(const float* __restrict__ dw2, const float* __restrict__ dw3,
                              const float* __restrict__ dw4, const float* __restrict__ bw2,
                              const float* __restrict__ bw3, const float* __restrict__ bw4,
                              uint4* __restrict__ outF, uint4* __restrict__ outC) {
    int set = blockIdx.x, n = blockIdx.y;
    const float* wt; int coutr;
    switch (set) {
        case 0: wt = dw2 + (size_t)n * 32 * 32 * 9; coutr = 32; break;
        case 1: wt = dw3 + (size_t)n * 32 * 32 * 9; coutr = 32; break;
        case 2: wt = dw4 + (size_t)n * 32 * 9;      coutr = 1;  break;
        case 3: wt = bw2 + (size_t)n * 32 * 32 * 9; coutr = 32; break;
        case 4: wt = bw3 + (size_t)n * 32 * 32 * 9; coutr = 32; break;
        case 5: wt = bw4 + (size_t)n * 32 * 9;      coutr = 1;  break;
        case 6: wt = dw4 + (size_t)n * 32 * 9;      coutr = 1;  break;
        default: wt = bw4 + (size_t)n * 32 * 9;     coutr = 1;  break;
    }
    auto wval = [&](int kp, int oc, uint32_t& hi, uint32_t& lo) {
        int k0 = 2 * kp;
        int tap = k0 >> 5, ic = k0 & 31;
        float w0 = 0.f, w1 = 0.f;
        if (oc < coutr) {
            w0 = wt[(oc * 32 + ic) * 9 + tap];
            w1 = wt[(oc * 32 + ic + 1) * 9 + tap];
        }
        hi = pack_split(w0, w1, lo);
    };
    if (set < 6) {
        uint4* o = outF + ((size_t)n * 6 + set) * 2304;
        for (int e = threadIdx.x; e < 2304; e += 256) {
            int c = e >> 7, l3 = (e >> 5) & 3, oc = e & 31;
            int kpA = c * 8 + l3;
            uint32_t hA, lA, hB, lB;
            wval(kpA, oc, hA, lA);
            wval(kpA + 4, oc, hB, lB);
            o[e] = make_uint4(hA, hB, lA, lB);
        }
    } else {
        uint4* o = outC + ((size_t)n * 2 + (set - 6)) * 576;
        for (int e = threadIdx.x; e < 576; e += 256) {
            int c = e >> 5, l3 = (e >> 3) & 3, oc = e & 7;
            int kpA = c * 8 + l3;
            uint32_t hA, lA, hB, lB;
            wval(kpA, oc, hA, lA);
            wval(kpA + 4, oc, hB, lB);
            o[e] = make_uint4(hA, hB, lA, lB);
        }
    }
}

__device__ __forceinline__ int ximg_idx(int s, int gy, int gx) {
    int h = gy / 33, i = gy % 33, l = gx / 33, j = gx % 33;
    return (i * 33 + j) * NCOL + l * (NH * NS) + h * NS + s;
}

#define WSF_BYTES (72 * 34 * 16)   // 39168
#define WSC_BYTES (72 * 10 * 16)   // 11520
__device__ __forceinline__ void load_w4(const uint4* __restrict__ wp,
                                        uint4* __restrict__ ws, int tid) {
#pragma unroll
    for (int i = 0; i < 9; i++) {
        int e = i * 256 + tid;
        ws[(e >> 5) * 34 + (e & 31)] = wp[e];
    }
}
__device__ __forceinline__ void load_w4c(const uint4* __restrict__ wp,
                                         uint4* __restrict__ ws, int tid) {
#pragma unroll
    for (int i = 0; i < 3; i++) {
        int e = i * 256 + tid;
        if (e < 576) ws[(e >> 3) * 10 + (e & 7)] = wp[e];
    }
}

// wide tile constants
#define WP0 408
#define WP1 344
#define WNP0 (11 * 35)
#define WNP1 (34 * 10)

// ============ WIDE fused conv1+conv2 (256 px / block) ============================
template<int MODE>
__global__ void __launch_bounds__(256)
conv12_hmma(const float* __restrict__ xin,
            const float* __restrict__ w1g,
            const float* __restrict__ b1g,
            const uint4* __restrict__ wpack,
            const float* __restrict__ bias2,
            uint32_t* __restrict__ out) {
    extern __shared__ char smem[];
    constexpr int PSTR = (MODE == 0) ? WP0 : WP1;
    constexpr int WROW = (MODE == 0) ? 35 : 10;
    constexpr int NPOS = (MODE == 0) ? WNP0 : WNP1;
    constexpr int RW   = (MODE == 0) ? 37 : 12;
    constexpr int RAWN = (MODE == 0) ? 13 * 37 : 36 * 12;
    uint4* ws = (uint4*)smem;
    uint32_t* hhi = (uint32_t*)(smem + WSF_BYTES);
    float* raw = (float*)(smem + WSF_BYTES + 16 * PSTR * 4);
    float* w1s = raw + ((RAWN + 3) & ~3);

    const int tid = threadIdx.x;
    const int wid = tid >> 5;
    const int lane = tid & 31;
    const int rg = lane >> 2;
    const int l3 = lane & 3;
    const int kq = l3 * 2;

    int n_img, p0 = 0, y_first = 0, y0t = 0, x0t = 0;
    if (MODE == 0) {
        n_img = blockIdx.x / 5;
        p0 = (blockIdx.x % 5) * 256;
        y_first = p0 / 33;
    } else {
        int b = blockIdx.x;
        int tx = b % 33; b /= 33;
        int ty = b % 9; b /= 9;
        n_img = b; y0t = ty * 32; x0t = tx * 8;
    }

    load_w4(wpack, ws, tid);
    for (int e = tid; e < 320; e += 256)
        w1s[e] = (e < 288) ? w1g[e] : b1g[e - 288];
    if (MODE == 0) {
        for (int e = tid; e < RAWN; e += 256) {
            int ry = e / RW, rx = e % RW;
            int gy = y_first - 2 + ry, gx = rx - 2;
            bool ok = (gy >= 0) && (gy < 33) && (gx >= 0) && (gx < 33);
            raw[e] = ok ? xin[(gy * 33 + gx) * NCOL + n_img] : 0.f;
        }
    } else {
        for (int e = tid; e < RAWN; e += 256) {
            int ry = e / RW, rx = e % RW;
            int gy = y0t - 2 + ry, gx = x0t - 2 + rx;
            bool ok = (gy >= 0) && (gy < HP) && (gx >= 0) && (gx < HP);
            raw[e] = ok ? xin[ximg_idx(n_img, gy, gx)] : 0.f;
        }
    }
    __syncthreads();

    for (int q = tid; q < NPOS; q += 256) {
        int hy = q / WROW, hx = q % WROW;
        int gy, gx, GH, GW;
        if (MODE == 0) { gy = y_first - 1 + hy; gx = hx - 1; GH = 33; GW = 33; }
        else           { gy = y0t - 1 + hy;     gx = x0t - 1 + hx; GH = HP; GW = HP; }
        bool valid = (gy >= 0) && (gy < GH) && (gx >= 0) && (gx < GW);
        float c1[32];
        if (valid) {
            float t0 = raw[hy * RW + hx],     t1 = raw[hy * RW + hx + 1],     t2 = raw[hy * RW + hx + 2];
            float t3 = raw[(hy+1) * RW + hx], t4 = raw[(hy+1) * RW + hx + 1], t5 = raw[(hy+1) * RW + hx + 2];
            float t6 = raw[(hy+2) * RW + hx], t7 = raw[(hy+2) * RW + hx + 1], t8 = raw[(hy+2) * RW + hx + 2];
#pragma unroll
            for (int oc = 0; oc < 32; oc++) {
                const float* w = w1s + oc * 9;
                float s = w1s[288 + oc];
                s += t0*w[0] + t1*w[1] + t2*w[2]
                   + t3*w[3] + t4*w[4] + t5*w[5]
                   + t6*w[6] + t7*w[7] + t8*w[8];
                c1[oc] = fmaxf(s, 0.f);
            }
        } else {
#pragma unroll
            for (int oc = 0; oc < 32; oc++) c1[oc] = 0.f;
        }
#pragma unroll
        for (int p = 0; p < 16; p++)
            hhi[p * PSTR + q] = pack2(c1[2*p], c1[2*p+1]);
    }
    __syncthreads();

    const int m0 = wid * 16 + rg;
    int base[4];
#pragma unroll
    for (int q = 0; q < 4; q++) {
        int m = m0 + (q & 1) * 8 + (q >> 1) * 128;
        if (MODE == 0) {
            int p = p0 + m;
            int yl = p / 33;
            base[q] = (p < BBSZ) ? (yl - y_first) * 35 + (p - yl * 33) : 0;
        } else {
            base[q] = (m >> 3) * 10 + (m & 7);
        }
    }
    const uint32_t* ph = hhi + l3 * PSTR;

    float acc[2][4][4];
#pragma unroll
    for (int tt = 0; tt < 2; tt++)
#pragma unroll
        for (int nt = 0; nt < 4; nt++)
#pragma unroll
            for (int i = 0; i < 4; i++) acc[tt][nt][i] = 0.f;

#pragma unroll
    for (int t = 0; t < 9; t++) {
        const int toff = (t / 3) * WROW + (t % 3);
#pragma unroll
        for (int e2 = 0; e2 < 2; e2++) {
            const int c = 2 * t + e2;
            const int pb = e2 * 8 * PSTR + toff;
            uint32_t a0 = ph[base[0] + pb];
            uint32_t a1 = ph[base[1] + pb];
            uint32_t a2 = ph[base[0] + pb + 4 * PSTR];
            uint32_t a3 = ph[base[1] + pb + 4 * PSTR];
            uint32_t a4 = ph[base[2] + pb];
            uint32_t a5 = ph[base[3] + pb];
            uint32_t a6 = ph[base[2] + pb + 4 * PSTR];
            uint32_t a7 = ph[base[3] + pb + 4 * PSTR];
            const int row = (c * 4 + l3) * 34 + rg;
#pragma unroll
            for (int nt = 0; nt < 4; nt++) {
                uint4 B = ws[row + nt * 8];
                HMMA16816(acc[0][nt], a0, a1, a2, a3, B.x, B.y);
                HMMA16816(acc[0][nt], a0, a1, a2, a3, B.z, B.w);
                HMMA16816(acc[1][nt], a4, a5, a6, a7, B.x, B.y);
                HMMA16816(acc[1][nt], a4, a5, a6, a7, B.z, B.w);
            }
        }
    }

#pragma unroll
    for (int tt = 0; tt < 2; tt++) {
#pragma unroll
        for (int nt = 0; nt < 4; nt++) {
            int oc = nt * 8 + kq;
            int p2 = nt * 4 + l3;
            float b0 = bias2[oc], b1 = bias2[oc + 1];
            uint32_t h0 = pack2(fmaxf(acc[tt][nt][0] + b0, 0.f), fmaxf(acc[tt][nt][1] + b1, 0.f));
            uint32_t h1 = pack2(fmaxf(acc[tt][nt][2] + b0, 0.f), fmaxf(acc[tt][nt][3] + b1, 0.f));
            int m = m0 + tt * 128;
            if (MODE == 0) {
                int pl = p0 + m, phh = pl + 8;
                if (pl < BBSZ) out[(size_t)(n_img * 16 + p2) * BBSZ + pl] = h0;
                if (phh < BBSZ) out[(size_t)(n_img * 16 + p2) * BBSZ + phh] = h1;
            } else {
                int oyl = y0t + (m >> 3), oxl = x0t + (m & 7);
                int oyh = y0t + ((m + 8) >> 3), oxh = x0t + ((m + 8) & 7);
                if (oyl < HP) out[((size_t)(n_img * 16 + p2) * HP + oyl) * HP + oxl] = h0;
                if (oyh < HP) out[((size_t)(n_img * 16 + p2) * HP + oyh) * HP + oxh] = h1;
            }
        }
    }
}

// ============ WIDE mid conv (256 px / block, 32 oc) ==============================
template<int MODE>
__global__ void __launch_bounds__(256)
conv_hmma_w(const uint32_t* __restrict__ in,
            const uint4* __restrict__ wpack,
            const float* __restrict__ bias,
            uint32_t* __restrict__ out) {
    extern __shared__ char smem[];
    constexpr int PSTR = (MODE == 0) ? WP0 : WP1;
    constexpr int WROW = (MODE == 0) ? 35 : 10;
    constexpr int NPOS = (MODE == 0) ? WNP0 : WNP1;
    uint4* ws = (uint4*)smem;
    uint32_t* hhi = (uint32_t*)(smem + WSF_BYTES);

    const int tid = threadIdx.x;
    const int wid = tid >> 5;
    const int lane = tid & 31;
    const int rg = lane >> 2;
    const int l3 = lane & 3;
    const int kq = l3 * 2;

    int n_img, p0 = 0, y_first = 0, y0t = 0, x0t = 0;
    if (MODE == 0) {
        n_img = blockIdx.x / 5;
        p0 = (blockIdx.x % 5) * 256;
        y_first = p0 / 33;
    } else {
        int b = blockIdx.x;
        int tx = b % 33; b /= 33;
        int ty = b % 9; b /= 9;
        n_img = b; y0t = ty * 32; x0t = tx * 8;
    }

    load_w4(wpack, ws, tid);

    if (MODE == 0) {
        for (int e = tid; e < 16 * NPOS; e += 256) {
            int pair = e / NPOS, pos = e % NPOS;
            int row = pos / 35, xp = pos % 35;
            int gy = y_first - 1 + row, gx = xp - 1;
            bool ok = (gy >= 0) && (gy < 33) && (xp >= 1) && (xp < 34);
            hhi[pair * PSTR + pos] =
                ok ? in[(size_t)(n_img * 16 + pair) * BBSZ + gy * 33 + gx] : 0u;
        }
    } else {
        for (int e = tid; e < 16 * NPOS; e += 256) {
            int pair = e / NPOS, pos = e % NPOS;
            int row = pos / 10, xp = pos % 10;
            int gy = y0t - 1 + row, gx = x0t - 1 + xp;
            bool ok = (gy >= 0) && (gy < HP) && (gx >= 0) && (gx < HP);
            hhi[pair * PSTR + pos] =
                ok ? in[((size_t)(n_img * 16 + pair) * HP + gy) * HP + gx] : 0u;
        }
    }
    __syncthreads();

    const int m0 = wid * 16 + rg;
    int base[4];
#pragma unroll
    for (int q = 0; q < 4; q++) {
        int m = m0 + (q & 1) * 8 + (q >> 1) * 128;
        if (MODE == 0) {
            int p = p0 + m;
            int yl = p / 33;
            base[q] = (p < BBSZ) ? (yl - y_first) * 35 + (p - yl * 33) : 0;
        } else {
            base[q] = (m >> 3) * 10 + (m & 7);
        }
    }
    const uint32_t* ph = hhi + l3 * PSTR;

    float acc[2][4][4];
#pragma unroll
    for (int tt = 0; tt < 2; tt++)
#pragma unroll
        for (int nt = 0; nt < 4; nt++)
#pragma unroll
            for (int i = 0; i < 4; i++) acc[tt][nt][i] = 0.f;

#pragma unroll
    for (int t = 0; t < 9; t++) {
        const int toff = (t / 3) * WROW + (t % 3);
#pragma unroll
        for (int e2 = 0; e2 < 2; e2++) {
            const int c = 2 * t + e2;
            const int pb = e2 * 8 * PSTR + toff;
            uint32_t a0 = ph[base[0] + pb];
            uint32_t a1 = ph[base[1] + pb];
            uint32_t a2 = ph[base[0] + pb + 4 * PSTR];
            uint32_t a3 = ph[base[1] + pb + 4 * PSTR];
            uint32_t a4 = ph[base[2] + pb];
            uint32_t a5 = ph[base[3] + pb];
            uint32_t a6 = ph[base[2] + pb + 4 * PSTR];
            uint32_t a7 = ph[base[3] + pb + 4 * PSTR];
            const int row = (c * 4 + l3) * 34 + rg;
#pragma unroll
            for (int nt = 0; nt < 4; nt++) {
                uint4 B = ws[row + nt * 8];
                HMMA16816(acc[0][nt], a0, a1, a2, a3, B.x, B.y);
                HMMA16816(acc[0][nt], a0, a1, a2, a3, B.z, B.w);
                HMMA16816(acc[1][nt], a4, a5, a6, a7, B.x, B.y);
                HMMA16816(acc[1][nt], a4, a5, a6, a7, B.z, B.w);
            }
        }
    }

#pragma unroll
    for (int tt = 0; tt < 2; tt++) {
#pragma unroll
        for (int nt = 0; nt < 4; nt++) {
            int oc = nt * 8 + kq;
            int p2 = nt * 4 + l3;
            float b0 = bias[oc], b1 = bias[oc + 1];
            uint32_t h0 = pack2(fmaxf(acc[tt][nt][0] + b0, 0.f), fmaxf(acc[tt][nt][1] + b1, 0.f));
            uint32_t h1 = pack2(fmaxf(acc[tt][nt][2] + b0, 0.f), fmaxf(acc[tt][nt][3] + b1, 0.f));
            int m = m0 + tt * 128;
            if (MODE == 0) {
                int pl = p0 + m, phh = pl + 8;
                if (pl < BBSZ) out[(size_t)(n_img * 16 + p2) * BBSZ + pl] = h0;
                if (phh < BBSZ) out[(size_t)(n_img * 16 + p2) * BBSZ + phh] = h1;
            } else {
                int oyl = y0t + (m >> 3), oxl = x0t + (m & 7);
                int oyh = y0t + ((m + 8) >> 3), oxh = x0t + ((m + 8) & 7);
                if (oyl < HP) out[((size_t)(n_img * 16 + p2) * HP + oyl) * HP + oxl] = h0;
                if (oyh < HP) out[((size_t)(n_img * 16 + p2) * HP + oyh) * HP + oxh] = h1;
            }
        }
    }
}

// ---------------- WIDE conv4 (256 px / block, 1 oc) ------------------------------
// OUTM 1: col-major float out ; OUTM 3: X -= D (blockify map)
template<int MODE, int OUTM>
__global__ void __launch_bounds__(256)
conv_hmma_n(const uint32_t* __restrict__ in,
            const uint4* __restrict__ wpack,
            float* __restrict__ out) {
    extern __shared__ char smem[];
    uint4* ws = (uint4*)smem;
    constexpr int PSTR = (MODE == 0) ? WP0 : WP1;
    constexpr int WROW = (MODE == 0) ? 35 : 10;
    constexpr int NPOS = (MODE == 0) ? WNP0 : WNP1;
    uint32_t* hhi = (uint32_t*)(smem + WSC_BYTES);

    const int tid = threadIdx.x;
    const int wid = tid >> 5;
    const int lane = tid & 31;
    const int rg = lane >> 2;
    const int l3 = lane & 3;

    int n_img, p0 = 0, y_first = 0, y0t = 0, x0t = 0;
    if (MODE == 0) {
        n_img = blockIdx.x / 5;
        p0 = (blockIdx.x % 5) * 256;
        y_first = p0 / 33;
    } else {
        int b = blockIdx.x;
        int tx = b % 33; b /= 33;
        int ty = b % 9; b /= 9;
        n_img = b; y0t = ty * 32; x0t = tx * 8;
    }

    load_w4c(wpack, ws, tid);

    if (MODE == 0) {
        for (int e = tid; e < 16 * NPOS; e += 256) {
            int pair = e / NPOS, pos = e % NPOS;
            int row = pos / 35, xp = pos % 35;
            int gy = y_first - 1 + row, gx = xp - 1;
            bool ok = (gy >= 0) && (gy < 33) && (xp >= 1) && (xp < 34);
            hhi[pair * PSTR + pos] =
                ok ? in[(size_t)(n_img * 16 + pair) * BBSZ + gy * 33 + gx] : 0u;
        }
    } else {
        for (int e = tid; e < 16 * NPOS; e += 256) {
            int pair = e / NPOS, pos = e % NPOS;
            int row = pos / 10, xp = pos % 10;
            int gy = y0t - 1 + row, gx = x0t - 1 + xp;
            bool ok = (gy >= 0) && (gy < HP) && (gx >= 0) && (gx < HP);
            hhi[pair * PSTR + pos] =
                ok ? in[((size_t)(n_img * 16 + pair) * HP + gy) * HP + gx] : 0u;
        }
    }
    __syncthreads();

    const int m0 = wid * 16 + rg;
    int base[4];
#pragma unroll
    for (int q = 0; q < 4; q++) {
        int m = m0 + (q & 1) * 8 + (q >> 1) * 128;
        if (MODE == 0) {
            int p = p0 + m;
            int yl = p / 33;
            base[q] = (p < BBSZ) ? (yl - y_first) * 35 + (p - yl * 33) : 0;
        } else {
            base[q] = (m >> 3) * 10 + (m & 7);
        }
    }
    const uint32_t* ph = hhi + l3 * PSTR;

    float acc[2][4];
#pragma unroll
    for (int tt = 0; tt < 2; tt++)
#pragma unroll
        for (int i = 0; i < 4; i++) acc[tt][i] = 0.f;

#pragma unroll
    for (int t = 0; t < 9; t++) {
        const int toff = (t / 3) * WROW + (t % 3);
#pragma unroll
        for (int e2 = 0; e2 < 2; e2++) {
            const int c = 2 * t + e2;
            const int pb = e2 * 8 * PSTR + toff;
            uint32_t a0 = ph[base[0] + pb];
            uint32_t a1 = ph[base[1] + pb];
            uint32_t a2 = ph[base[0] + pb + 4 * PSTR];
            uint32_t a3 = ph[base[1] + pb + 4 * PSTR];
            uint32_t a4 = ph[base[2] + pb];
            uint32_t a5 = ph[base[3] + pb];
            uint32_t a6 = ph[base[2] + pb + 4 * PSTR];
            uint32_t a7 = ph[base[3] + pb + 4 * PSTR];
            uint4 B = ws[(c * 4 + l3) * 10 + rg];
            HMMA16816(acc[0], a0, a1, a2, a3, B.x, B.y);
            HMMA16816(acc[0], a0, a1, a2, a3, B.z, B.w);
            HMMA16816(acc[1], a4, a5, a6, a7, B.x, B.y);
            HMMA16816(acc[1], a4, a5, a6, a7, B.z, B.w);
        }
    }

    if (l3 == 0) {
#pragma unroll
        for (int tt = 0; tt < 2; tt++) {
            int m = m0 + tt * 128;
            if (OUTM == 1) {
                int pl = p0 + m, phh = pl + 8;
                if (pl < BBSZ) out[(size_t)pl * NCOL + n_img] = acc[tt][0];
                if (phh < BBSZ) out[(size_t)phh * NCOL + n_img] = acc[tt][2];
            } else {
                int gyl = y0t + (m >> 3), gxl = x0t + (m & 7);
                int gyh = y0t + ((m + 8) >> 3), gxh = x0t + ((m + 8) & 7);
                if (gyl < HP) { int ix = ximg_idx(n_img, gyl, gxl); out[ix] -= acc[tt][0]; }
                if (gyh < HP) { int ix = ximg_idx(n_img, gyh, gxh); out[ix] -= acc[tt][2]; }
            }
        }
    }
}

// ---------------- blockify / unblockify ------------------------------------------
__global__ void blockify_input_kernel(const float* __restrict__ in, float* __restrict__ Xb) {
    int idx = blockIdx.x * blockDim.x + threadIdx.x;
    if (idx >= BBSZ * NCOL) return;
    int r = idx / NCOL, n = idx % NCOL;
    int i = r / BQ, j = r % BQ;
    int l = n / (NH * NS), h = (n / NS) % NH, s = n % NS;
    Xb[idx] = in[(s * HP + h * BQ + i) * HP + l * BQ + j];
}
__global__ void unblockify_kernel(const float* __restrict__ X, float* __restrict__ img) {
    int idx = blockIdx.x * blockDim.x + threadIdx.x;
    if (idx >= IMGPIX) return;
    int s = idx / (HP * HP);
    int rem = idx % (HP * HP);
    int R = rem / HP, C = rem % HP;
    int h = R / BQ, i = R % BQ, l = C / BQ, j = C % BQ;
    img[idx] = X[(i * BQ + j) * NCOL + (l * (NH * NS) + h * NS + s)];
}

// ---------------- host driver ------------------------------------------------------
extern "C" void kernel_launch(void* const* d_in, const int* in_sizes, int n_in,
                              void* d_out, int out_size) {
    const float* inputs = (const float*)d_in[0];
    const float* A      = (const float*)d_in[1];
    const float* Q      = (const float*)d_in[2];
    const float* steps  = (const float*)d_in[3];
    const float* den_w1 = (const float*)d_in[4];
    const float* den_b1 = (const float*)d_in[5];
    const float* den_w2 = (const float*)d_in[6];
    const float* den_b2 = (const float*)d_in[7];
    const float* den_w3 = (const float*)d_in[8];
    const float* den_b3 = (const float*)d_in[9];
    const float* den_w4 = (const float*)d_in[10];
    const float* deb_w1 = (const float*)d_in[11];
    const float* deb_b1 = (const float*)d_in[12];
    const float* deb_w2 = (const float*)d_in[13];
    const float* deb_b2 = (const float*)d_in[14];
    const float* deb_w3 = (const float*)d_in[15];
    const float* deb_b3 = (const float*)d_in[16];
    const float* deb_w4 = (const float*)d_in[17];
    int layers = in_sizes[3];

    float *pX, *pY, *pR, *pZ, *pN, *pAtA;
    uint32_t *pT1, *pT2, *pmA, *pmAT, *pmQ, *pmAtA;
    uint4 *pW4, *pW4c;
    cudaGetSymbolAddress((void**)&pX, g_X);
    cudaGetSymbolAddress((void**)&pY, g_y);
    cudaGetSymbolAddress((void**)&pR, g_r);
    cudaGetSymbolAddress((void**)&pZ, g_z);
    cudaGetSymbolAddress((void**)&pN, g_noise);
    cudaGetSymbolAddress((void**)&pAtA, g_AtA);
    cudaGetSymbolAddress((void**)&pT1, g_t1);
    cudaGetSymbolAddress((void**)&pT2, g_t2);
    cudaGetSymbolAddress((void**)&pW4, g_wpack4);
    cudaGetSymbolAddress((void**)&pW4c, g_wpack4c);
    cudaGetSymbolAddress((void**)&pmA, g_mA);
    cudaGetSymbolAddress((void**)&pmAT, g_mAT);
    cudaGetSymbolAddress((void**)&pmQ, g_mQ);
    cudaGetSymbolAddress((void**)&pmAtA, g_mAtA);

    const int EW = 256;
    const int EG = (IMGPIX + EW - 1) / EW;

    const int SM0W = WSF_BYTES + 16 * WP0 * 4;                    // 65280
    const int SM1W = WSF_BYTES + 16 * WP1 * 4;                    // 61184
    const int SM0C = WSC_BYTES + 16 * WP0 * 4;                    // 37632
    const int SM1C = WSC_BYTES + 16 * WP1 * 4;                    // 33536
    const int SM12_0 = SM0W + ((13 * 37 + 3) & ~3) * 4 + 320 * 4;
    const int SM12_1 = SM1W + ((36 * 12 + 3) & ~3) * 4 + 320 * 4;
    cudaFuncSetAttribute(conv12_hmma<0>, cudaFuncAttributeMaxDynamicSharedMemorySize, SM12_0);
    cudaFuncSetAttribute(conv12_hmma<1>, cudaFuncAttributeMaxDynamicSharedMemorySize, SM12_1);
    cudaFuncSetAttribute(conv_hmma_w<0>, cudaFuncAttributeMaxDynamicSharedMemorySize, SM0W);
    cudaFuncSetAttribute(conv_hmma_w<1>, cudaFuncAttributeMaxDynamicSharedMemorySize, SM1W);
    cudaFuncSetAttribute(conv_hmma_n<0,1>, cudaFuncAttributeMaxDynamicSharedMemorySize, SM0C);
    cudaFuncSetAttribute(conv_hmma_n<1,3>, cudaFuncAttributeMaxDynamicSharedMemorySize, SM1C);

    const int G0W = NCOL * 5;        // 2560
    const int G1W = 8 * 9 * 33;      // 2376

    const int PS_A   = 545 * 272;
    const int PS_ATQ = 136 * 1092;
    const int PS_AtA = 545 * 1092;

    prep_weights4<<<dim3(8, layers), 256>>>(den_w2, den_w3, den_w4,
                                            deb_w2, deb_w3, deb_w4, pW4, pW4c);
    blockify_input_kernel<<<EG, EW>>>(inputs, pZ);
    prep_mat<<<580, 256>>>(A, 1089, 0, 272, 1089, 272, pmA);
    prep_mat<<<580, 256>>>(A, 1089, 1, 1089, 272, 1092, pmAT);
    prep_mat<<<580, 256>>>(Q, 272, 0, 1089, 272, 1092, pmQ);
    hgemm<0><<<dim3(16, 3), 256>>>(pmA, PS_A, 272, pZ, pY, 272, 512, 1089,
                                   nullptr, nullptr, nullptr, 0);
    hgemm<0><<<dim3(16, 9), 256>>>(pmQ, PS_ATQ, 1092, pY, pX, 1089, 512, 272,
                                   nullptr, nullptr, nullptr, 0);
    hgemm<0><<<dim3(35, 9), 256>>>(pmAT, PS_ATQ, 1092, A, pAtA, 1089, 1089, 272,
                                   nullptr, nullptr, nullptr, 0);
    prep_mat<<<2325, 256>>>(pAtA, 1089, 0, 1089, 1089, 1092, pmAtA);

    for (int n = 0; n < layers; n++) {
        const uint4* wf = pW4 + (size_t)(n * 6) * 2304;
        const uint4* wc = pW4c + (size_t)(n * 2) * 576;
        hgemm<1><<<dim3(16, 3), 256>>>(pmA, PS_A, 272, pX, pR, 272, 512, 1089,
                                       pY, nullptr, nullptr, 0);
        hgemm<2><<<dim3(16, 9), 256>>>(pmAT, PS_ATQ, 1092, pR, pZ, 1089, 512, 272,
                                       pX, nullptr, steps, n);
        conv12_hmma<0><<<G0W, 256, SM12_0>>>(pX, den_w1 + (size_t)n * 32 * 9,
                                             den_b1 + n * 32, wf + 0 * 2304,
                                             den_b2 + n * 32, pT1);
        conv_hmma_w<0><<<G0W, 256, SM0W>>>(pT1, wf + 1 * 2304, den_b3 + n * 32, pT2);
        conv_hmma_n<0,1><<<G0W, 256, SM0C>>>(pT2, wc + 0 * 576, pN);
        hgemm<3><<<dim3(16, 9), 256>>>(pmAtA, PS_AtA, 1092, pN, pX, 1089, 512, 1089,
                                       pZ, pN, steps, n);
        conv12_hmma<1><<<G1W, 256, SM12_1>>>(pX, deb_w1 + (size_t)n * 32 * 9,
                                             deb_b1 + n * 32, wf + 3 * 2304,
                                             deb_b2 + n * 32, pT1);
        conv_hmma_w<1><<<G1W, 256, SM1W>>>(pT1, wf + 4 * 2304, deb_b3 + n * 32, pT2);
        conv_hmma_n<1,3><<<G1W, 256, SM1C>>>(pT2, wc + 1 * 576, pX);
    }

    unblockify_kernel<<<EG, EW>>>(pX, (float*)d_out);
}

// round 17
// speedup vs baseline: 1.2013x; 1.1112x over previous
#include <cuda_runtime.h>
#include <cuda_fp16.h>
#include <cstdint>

#define BQ   33
#define BBSZ 1089
#define NS   8
#define NH   8
#define NL   8
#define NCOL 512
#define MROW 272
#define HP   264
#define IMGPIX (NS*HP*HP)
#define PLN  8921088

// ---------------- scratch ----------------------------------------------------
__device__ float g_X[BBSZ * NCOL];
__device__ float g_y[MROW * NCOL];
__device__ float g_r[MROW * NCOL];
__device__ float g_z[BBSZ * NCOL];
__device__ float g_noise[BBSZ * NCOL];
__device__ float g_AtA[BBSZ * BBSZ];
__device__ uint32_t g_t1[PLN];
__device__ uint32_t g_t2[PLN];
__device__ uint4 g_wpack4[8 * 6 * 2304];
__device__ uint4 g_wpack4c[8 * 2 * 576];
__device__ uint32_t g_mA[2 * 545 * 272];
__device__ uint32_t g_mAT[2 * 136 * 1092];
__device__ uint32_t g_mQ[2 * 136 * 1092];
__device__ uint32_t g_mAtA[2 * 545 * 1092];

// ---------------- HMMA helpers ------------------------------------------------
#define HMMA16816(c, a0, a1, a2, a3, b0, b1) \
    asm volatile("mma.sync.aligned.m16n8k16.row.col.f32.f16.f16.f32 " \
        "{%0,%1,%2,%3}, {%4,%5,%6,%7}, {%8,%9}, {%0,%1,%2,%3};" \
        : "+f"((c)[0]), "+f"((c)[1]), "+f"((c)[2]), "+f"((c)[3]) \
        : "r"(a0), "r"(a1), "r"(a2), "r"(a3), "r"(b0), "r"(b1))

__device__ __forceinline__ uint32_t h2bits(__half2 h) {
    return *reinterpret_cast<uint32_t*>(&h);
}
__device__ __forceinline__ uint32_t pack2(float x, float y) {
    __half2 h = __floats2half2_rn(x, y);
    return h2bits(h);
}
__device__ __forceinline__ uint32_t pack_split(float x, float y, uint32_t& lo) {
    __half2 h = __floats2half2_rn(x, y);
    __half2 l = __floats2half2_rn(x - __low2float(h), y - __high2float(h));
    lo = h2bits(l);
    return h2bits(h);
}

// ---------------- matrix pre-pack ----------------------------------------------
__global__ void prep_mat(const float* __restrict__ src, int lds, int trans,
                         int M, int K, int Mp, uint32_t* __restrict__ dst) {
    int PS = ((K + 1) >> 1) * Mp;
    for (int e = blockIdx.x * blockDim.x + threadIdx.x; e < PS;
         e += gridDim.x * blockDim.x) {
        int m = e % Mp, kp = e / Mp;
        int k0 = 2 * kp;
        float w0 = 0.f, w1 = 0.f;
        if (m < M) {
            if (k0 < K)     w0 = trans ? src[(size_t)k0 * lds + m] : src[(size_t)m * lds + k0];
            if (k0 + 1 < K) w1 = trans ? src[(size_t)(k0 + 1) * lds + m] : src[(size_t)m * lds + k0 + 1];
        }
        uint32_t lo;
        uint32_t hi = pack_split(w0, w1, lo);
        dst[e] = hi;
        dst[PS + e] = lo;
    }
}

// ---------------- HMMA GEMM: BM=64, BN=32, 8 warps (4 m-tiles x 2 nt-groups) -----
template<int EPI>
__global__ void __launch_bounds__(256) hgemm(
    const uint32_t* __restrict__ Wp, int PS, int Mp,
    const float* __restrict__ X, float* __restrict__ C,
    int M, int N, int K,
    const float* __restrict__ E1, const float* __restrict__ E2,
    const float* __restrict__ stepsPtr, int stepIdx) {
    __shared__ uint2 Wsm[32 * 68];
    __shared__ uint2 Xsm[32 * 36];

    const int tid = threadIdx.x;
    const int wid = tid >> 5;
    const int lane = tid & 31;
    const int rg = lane >> 2;
    const int l3 = lane & 3;
    const int mt = wid & 3;          // m-tile 0..3
    const int ng = wid >> 2;         // nt-group 0..1
    const int bn = blockIdx.x * 32;
    const int bm = blockIdx.y * 64;
    const int mloc = mt * 16 + rg;
    const int KpTot = (K + 1) >> 1;
    const int nCh = (KpTot + 31) >> 5;

    float acc[2][4];
#pragma unroll
    for (int ntl = 0; ntl < 2; ntl++)
#pragma unroll
        for (int i = 0; i < 4; i++) acc[ntl][i] = 0.f;

    for (int ch = 0; ch < nCh; ch++) {
        int kp0 = ch * 32;
#pragma unroll
        for (int i = 0; i < 8; i++) {
            int e = i * 256 + tid;
            int m = e & 63, kp = e >> 6;
            int kpg = kp0 + kp, gm = bm + m;
            uint32_t hi = 0, lo = 0;
            if (kpg < KpTot && gm < Mp) {
                size_t off = (size_t)kpg * Mp + gm;
                hi = Wp[off];
                lo = Wp[PS + off];
            }
            Wsm[kp * 68 + m] = make_uint2(hi, lo);
        }
#pragma unroll
        for (int i = 0; i < 4; i++) {
            int e = i * 256 + tid;
            int n = e & 31, kp = e >> 5;
            int kpg = kp0 + kp, gn = bn + n;
            float f0 = 0.f, f1 = 0.f;
            int k0 = 2 * kpg;
            if (gn < N && k0 < K) {
                f0 = X[(size_t)k0 * N + gn];
                if (k0 + 1 < K) f1 = X[(size_t)(k0 + 1) * N + gn];
            }
            uint32_t lo;
            uint32_t hi = pack_split(f0, f1, lo);
            Xsm[kp * 36 + n] = make_uint2(hi, lo);
        }
        __syncthreads();
#pragma unroll
        for (int c = 0; c < 4; c++) {
            int kl = c * 8 + l3;
            uint2 A0 = Wsm[kl * 68 + mloc];
            uint2 A1 = Wsm[kl * 68 + mloc + 8];
            uint2 A2 = Wsm[(kl + 4) * 68 + mloc];
            uint2 A3 = Wsm[(kl + 4) * 68 + mloc + 8];
#pragma unroll
            for (int ntl = 0; ntl < 2; ntl++) {
                int nt = ng * 2 + ntl;
                uint2 B0 = Xsm[kl * 36 + nt * 8 + rg];
                uint2 B1 = Xsm[(kl + 4) * 36 + nt * 8 + rg];
                HMMA16816(acc[ntl], A0.x, A1.x, A2.x, A3.x, B0.x, B1.x);
                HMMA16816(acc[ntl], A0.x, A1.x, A2.x, A3.x, B0.y, B1.y);
                HMMA16816(acc[ntl], A0.y, A1.y, A2.y, A3.y, B0.x, B1.x);
            }
        }
        __syncthreads();
    }

    float step = (stepsPtr != nullptr) ? stepsPtr[stepIdx] : 0.f;
    int gml = bm + mloc;
#pragma unroll
    for (int ntl = 0; ntl < 2; ntl++) {
        int nt = ng * 2 + ntl;
        int gn0 = bn + nt * 8 + (l3 << 1);
#pragma unroll
        for (int half = 0; half < 2; half++) {
            int gm = gml + half * 8;
            if (gm >= M) continue;
#pragma unroll
            for (int q = 0; q < 2; q++) {
                int col = gn0 + q;
                if (col >= N) continue;
                size_t idx = (size_t)gm * N + col;
                float v = acc[ntl][half * 2 + q];
                float o;
                if (EPI == 0)      o = v;
                else if (EPI == 1) o = E1[idx] - v;
                else if (EPI == 2) o = step * v + E1[idx];
                else               o = E1[idx] - step * v + E2[idx];
                C[idx] = o;
            }
        }
    }
}

// ---------------- conv weight pre-pack: uint4 fragments --------------------------
__global__ void prep_weights4(const float* __restrict__ dw2, const float* __restrict__ dw3,
                              const float* __restrict__ dw4, const float* __restrict__ bw2,
                              const float* __restrict__ bw3, const float* __restrict__ bw4,
                              uint4* __restrict__ outF, uint4* __restrict__ outC) {
    int set = blockIdx.x, n = blockIdx.y;
    const float* wt; int coutr;
    switch (set) {
        case 0: wt = dw2 + (size_t)n * 32 * 32 * 9; coutr = 32; break;
        case 1: wt = dw3 + (size_t)n * 32 * 32 * 9; coutr = 32; break;
        case 2: wt = dw4 + (size_t)n * 32 * 9;      coutr = 1;  break;
        case 3: wt = bw2 + (size_t)n * 32 * 32 * 9; coutr = 32; break;
        case 4: wt = bw3 + (size_t)n * 32 * 32 * 9; coutr = 32; break;
        case 5: wt = bw4 + (size_t)n * 32 * 9;      coutr = 1;  break;
        case 6: wt = dw4 + (size_t)n * 32 * 9;      coutr = 1;  break;
        default: wt = bw4 + (size_t)n * 32 * 9;     coutr = 1;  break;
    }
    auto wval = [&](int kp, int oc, uint32_t& hi, uint32_t& lo) {
        int k0 = 2 * kp;
        int tap = k0 >> 5, ic = k0 & 31;
        float w0 = 0.f, w1 = 0.f;
        if (oc < coutr) {
            w0 = wt[(oc * 32 + ic) * 9 + tap];
            w1 = wt[(oc * 32 + ic + 1) * 9 + tap];
        }
        hi = pack_split(w0, w1, lo);
    };
    if (set < 6) {
        uint4* o = outF + ((size_t)n * 6 + set) * 2304;
        for (int e = threadIdx.x; e < 2304; e += 256) {
            int c = e >> 7, l3 = (e >> 5) & 3, oc = e & 31;
            int kpA = c * 8 + l3;
            uint32_t hA, lA, hB, lB;
            wval(kpA, oc, hA, lA);
            wval(kpA + 4, oc, hB, lB);
            o[e] = make_uint4(hA, hB, lA, lB);
        }
    } else {
        uint4* o = outC + ((size_t)n * 2 + (set - 6)) * 576;
        for (int e = threadIdx.x; e < 576; e += 256) {
            int c = e >> 5, l3 = (e >> 3) & 3, oc = e & 7;
            int kpA = c * 8 + l3;
            uint32_t hA, lA, hB, lB;
            wval(kpA, oc, hA, lA);
            wval(kpA + 4, oc, hB, lB);
            o[e] = make_uint4(hA, hB, lA, lB);
        }
    }
}

__device__ __forceinline__ int ximg_idx(int s, int gy, int gx) {
    int h = gy / 33, i = gy % 33, l = gx / 33, j = gx % 33;
    return (i * 33 + j) * NCOL + l * (NH * NS) + h * NS + s;
}

#define WSF_BYTES (72 * 34 * 16)   // 39168
#define WSC_BYTES (72 * 10 * 16)   // 11520
__device__ __forceinline__ void load_w4(const uint4* __restrict__ wp,
                                        uint4* __restrict__ ws, int tid) {
#pragma unroll
    for (int i = 0; i < 9; i++) {
        int e = i * 256 + tid;
        ws[(e >> 5) * 34 + (e & 31)] = wp[e];
    }
}
__device__ __forceinline__ void load_w4c(const uint4* __restrict__ wp,
                                         uint4* __restrict__ ws, int tid) {
#pragma unroll
    for (int i = 0; i < 3; i++) {
        int e = i * 256 + tid;
        if (e < 576) ws[(e >> 3) * 10 + (e & 7)] = wp[e];
    }
}

// wide tile constants
#define WP0 408
#define WP1 344
#define WNP0 (11 * 35)
#define WNP1 (34 * 10)

// ============ WIDE fused conv1+conv2 (256 px / block) ============================
template<int MODE>
__global__ void __launch_bounds__(256)
conv12_hmma(const float* __restrict__ xin,
            const float* __restrict__ w1g,
            const float* __restrict__ b1g,
            const uint4* __restrict__ wpack,
            const float* __restrict__ bias2,
            uint32_t* __restrict__ out) {
    extern __shared__ char smem[];
    constexpr int PSTR = (MODE == 0) ? WP0 : WP1;
    constexpr int WROW = (MODE == 0) ? 35 : 10;
    constexpr int NPOS = (MODE == 0) ? WNP0 : WNP1;
    constexpr int RW   = (MODE == 0) ? 37 : 12;
    constexpr int RAWN = (MODE == 0) ? 13 * 37 : 36 * 12;
    uint4* ws = (uint4*)smem;
    uint32_t* hhi = (uint32_t*)(smem + WSF_BYTES);
    float* raw = (float*)(smem + WSF_BYTES + 16 * PSTR * 4);
    float* w1s = raw + ((RAWN + 3) & ~3);

    const int tid = threadIdx.x;
    const int wid = tid >> 5;
    const int lane = tid & 31;
    const int rg = lane >> 2;
    const int l3 = lane & 3;
    const int kq = l3 * 2;

    int n_img, p0 = 0, y_first = 0, y0t = 0, x0t = 0;
    if (MODE == 0) {
        n_img = blockIdx.x / 5;
        p0 = (blockIdx.x % 5) * 256;
        y_first = p0 / 33;
    } else {
        int b = blockIdx.x;
        int tx = b % 33; b /= 33;
        int ty = b % 9; b /= 9;
        n_img = b; y0t = ty * 32; x0t = tx * 8;
    }

    load_w4(wpack, ws, tid);
    for (int e = tid; e < 320; e += 256)
        w1s[e] = (e < 288) ? w1g[e] : b1g[e - 288];
    if (MODE == 0) {
        for (int e = tid; e < RAWN; e += 256) {
            int ry = e / RW, rx = e % RW;
            int gy = y_first - 2 + ry, gx = rx - 2;
            bool ok = (gy >= 0) && (gy < 33) && (gx >= 0) && (gx < 33);
            raw[e] = ok ? xin[(gy * 33 + gx) * NCOL + n_img] : 0.f;
        }
    } else {
        for (int e = tid; e < RAWN; e += 256) {
            int ry = e / RW, rx = e % RW;
            int gy = y0t - 2 + ry, gx = x0t - 2 + rx;
            bool ok = (gy >= 0) && (gy < HP) && (gx >= 0) && (gx < HP);
            raw[e] = ok ? xin[ximg_idx(n_img, gy, gx)] : 0.f;
        }
    }
    __syncthreads();

    for (int q = tid; q < NPOS; q += 256) {
        int hy = q / WROW, hx = q % WROW;
        int gy, gx, GH, GW;
        if (MODE == 0) { gy = y_first - 1 + hy; gx = hx - 1; GH = 33; GW = 33; }
        else           { gy = y0t - 1 + hy;     gx = x0t - 1 + hx; GH = HP; GW = HP; }
        bool valid = (gy >= 0) && (gy < GH) && (gx >= 0) && (gx < GW);
        float c1[32];
        if (valid) {
            float t0 = raw[hy * RW + hx],     t1 = raw[hy * RW + hx + 1],     t2 = raw[hy * RW + hx + 2];
            float t3 = raw[(hy+1) * RW + hx], t4 = raw[(hy+1) * RW + hx + 1], t5 = raw[(hy+1) * RW + hx + 2];
            float t6 = raw[(hy+2) * RW + hx], t7 = raw[(hy+2) * RW + hx + 1], t8 = raw[(hy+2) * RW + hx + 2];
#pragma unroll
            for (int oc = 0; oc < 32; oc++) {
                const float* w = w1s + oc * 9;
                float s = w1s[288 + oc];
                s += t0*w[0] + t1*w[1] + t2*w[2]
                   + t3*w[3] + t4*w[4] + t5*w[5]
                   + t6*w[6] + t7*w[7] + t8*w[8];
                c1[oc] = fmaxf(s, 0.f);
            }
        } else {
#pragma unroll
            for (int oc = 0; oc < 32; oc++) c1[oc] = 0.f;
        }
#pragma unroll
        for (int p = 0; p < 16; p++)
            hhi[p * PSTR + q] = pack2(c1[2*p], c1[2*p+1]);
    }
    __syncthreads();

    const int m0 = wid * 16 + rg;
    int base[4];
#pragma unroll
    for (int q = 0; q < 4; q++) {
        int m = m0 + (q & 1) * 8 + (q >> 1) * 128;
        if (MODE == 0) {
            int p = p0 + m;
            int yl = p / 33;
            base[q] = (p < BBSZ) ? (yl - y_first) * 35 + (p - yl * 33) : 0;
        } else {
            base[q] = (m >> 3) * 10 + (m & 7);
        }
    }
    const uint32_t* ph = hhi + l3 * PSTR;

    float acc[2][4][4];
#pragma unroll
    for (int tt = 0; tt < 2; tt++)
#pragma unroll
        for (int nt = 0; nt < 4; nt++)
#pragma unroll
            for (int i = 0; i < 4; i++) acc[tt][nt][i] = 0.f;

#pragma unroll
    for (int t = 0; t < 9; t++) {
        const int toff = (t / 3) * WROW + (t % 3);
#pragma unroll
        for (int e2 = 0; e2 < 2; e2++) {
            const int c = 2 * t + e2;
            const int pb = e2 * 8 * PSTR + toff;
            uint32_t a0 = ph[base[0] + pb];
            uint32_t a1 = ph[base[1] + pb];
            uint32_t a2 = ph[base[0] + pb + 4 * PSTR];
            uint32_t a3 = ph[base[1] + pb + 4 * PSTR];
            uint32_t a4 = ph[base[2] + pb];
            uint32_t a5 = ph[base[3] + pb];
            uint32_t a6 = ph[base[2] + pb + 4 * PSTR];
            uint32_t a7 = ph[base[3] + pb + 4 * PSTR];
            const int row = (c * 4 + l3) * 34 + rg;
#pragma unroll
            for (int nt = 0; nt < 4; nt++) {
                uint4 B = ws[row + nt * 8];
                HMMA16816(acc[0][nt], a0, a1, a2, a3, B.x, B.y);
                HMMA16816(acc[0][nt], a0, a1, a2, a3, B.z, B.w);
                HMMA16816(acc[1][nt], a4, a5, a6, a7, B.x, B.y);
                HMMA16816(acc[1][nt], a4, a5, a6, a7, B.z, B.w);
            }
        }
    }

#pragma unroll
    for (int tt = 0; tt < 2; tt++) {
#pragma unroll
        for (int nt = 0; nt < 4; nt++) {
            int oc = nt * 8 + kq;
            int p2 = nt * 4 + l3;
            float b0 = bias2[oc], b1 = bias2[oc + 1];
            uint32_t h0 = pack2(fmaxf(acc[tt][nt][0] + b0, 0.f), fmaxf(acc[tt][nt][1] + b1, 0.f));
            uint32_t h1 = pack2(fmaxf(acc[tt][nt][2] + b0, 0.f), fmaxf(acc[tt][nt][3] + b1, 0.f));
            int m = m0 + tt * 128;
            if (MODE == 0) {
                int pl = p0 + m, phh = pl + 8;
                if (pl < BBSZ) out[(size_t)(n_img * 16 + p2) * BBSZ + pl] = h0;
                if (phh < BBSZ) out[(size_t)(n_img * 16 + p2) * BBSZ + phh] = h1;
            } else {
                int oyl = y0t + (m >> 3), oxl = x0t + (m & 7);
                int oyh = y0t + ((m + 8) >> 3), oxh = x0t + ((m + 8) & 7);
                if (oyl < HP) out[((size_t)(n_img * 16 + p2) * HP + oyl) * HP + oxl] = h0;
                if (oyh < HP) out[((size_t)(n_img * 16 + p2) * HP + oyh) * HP + oxh] = h1;
            }
        }
    }
}

// ============ WIDE mid conv (256 px / block, 32 oc) ==============================
template<int MODE>
__global__ void __launch_bounds__(256)
conv_hmma_w(const uint32_t* __restrict__ in,
            const uint4* __restrict__ wpack,
            const float* __restrict__ bias,
            uint32_t* __restrict__ out) {
    extern __shared__ char smem[];
    constexpr int PSTR = (MODE == 0) ? WP0 : WP1;
    constexpr int WROW = (MODE == 0) ? 35 : 10;
    constexpr int NPOS = (MODE == 0) ? WNP0 : WNP1;
    uint4* ws = (uint4*)smem;
    uint32_t* hhi = (uint32_t*)(smem + WSF_BYTES);

    const int tid = threadIdx.x;
    const int wid = tid >> 5;
    const int lane = tid & 31;
    const int rg = lane >> 2;
    const int l3 = lane & 3;
    const int kq = l3 * 2;

    int n_img, p0 = 0, y_first = 0, y0t = 0, x0t = 0;
    if (MODE == 0) {
        n_img = blockIdx.x / 5;
        p0 = (blockIdx.x % 5) * 256;
        y_first = p0 / 33;
    } else {
        int b = blockIdx.x;
        int tx = b % 33; b /= 33;
        int ty = b % 9; b /= 9;
        n_img = b; y0t = ty * 32; x0t = tx * 8;
    }

    load_w4(wpack, ws, tid);

    if (MODE == 0) {
        for (int e = tid; e < 16 * NPOS; e += 256) {
            int pair = e / NPOS, pos = e % NPOS;
            int row = pos / 35, xp = pos % 35;
            int gy = y_first - 1 + row, gx = xp - 1;
            bool ok = (gy >= 0) && (gy < 33) && (xp >= 1) && (xp < 34);
            hhi[pair * PSTR + pos] =
                ok ? in[(size_t)(n_img * 16 + pair) * BBSZ + gy * 33 + gx] : 0u;
        }
    } else {
        for (int e = tid; e < 16 * NPOS; e += 256) {
            int pair = e / NPOS, pos = e % NPOS;
            int row = pos / 10, xp = pos % 10;
            int gy = y0t - 1 + row, gx = x0t - 1 + xp;
            bool ok = (gy >= 0) && (gy < HP) && (gx >= 0) && (gx < HP);
            hhi[pair * PSTR + pos] =
                ok ? in[((size_t)(n_img * 16 + pair) * HP + gy) * HP + gx] : 0u;
        }
    }
    __syncthreads();

    const int m0 = wid * 16 + rg;
    int base[4];
#pragma unroll
    for (int q = 0; q < 4; q++) {
        int m = m0 + (q & 1) * 8 + (q >> 1) * 128;
        if (MODE == 0) {
            int p = p0 + m;
            int yl = p / 33;
            base[q] = (p < BBSZ) ? (yl - y_first) * 35 + (p - yl * 33) : 0;
        } else {
            base[q] = (m >> 3) * 10 + (m & 7);
        }
    }
    const uint32_t* ph = hhi + l3 * PSTR;

    float acc[2][4][4];
#pragma unroll
    for (int tt = 0; tt < 2; tt++)
#pragma unroll
        for (int nt = 0; nt < 4; nt++)
#pragma unroll
            for (int i = 0; i < 4; i++) acc[tt][nt][i] = 0.f;

#pragma unroll
    for (int t = 0; t < 9; t++) {
        const int toff = (t / 3) * WROW + (t % 3);
#pragma unroll
        for (int e2 = 0; e2 < 2; e2++) {
            const int c = 2 * t + e2;
            const int pb = e2 * 8 * PSTR + toff;
            uint32_t a0 = ph[base[0] + pb];
            uint32_t a1 = ph[base[1] + pb];
            uint32_t a2 = ph[base[0] + pb + 4 * PSTR];
            uint32_t a3 = ph[base[1] + pb + 4 * PSTR];
            uint32_t a4 = ph[base[2] + pb];
            uint32_t a5 = ph[base[3] + pb];
            uint32_t a6 = ph[base[2] + pb + 4 * PSTR];
            uint32_t a7 = ph[base[3] + pb + 4 * PSTR];
            const int row = (c * 4 + l3) * 34 + rg;
#pragma unroll
            for (int nt = 0; nt < 4; nt++) {
                uint4 B = ws[row + nt * 8];
                HMMA16816(acc[0][nt], a0, a1, a2, a3, B.x, B.y);
                HMMA16816(acc[0][nt], a0, a1, a2, a3, B.z, B.w);
                HMMA16816(acc[1][nt], a4, a5, a6, a7, B.x, B.y);
                HMMA16816(acc[1][nt], a4, a5, a6, a7, B.z, B.w);
            }
        }
    }

#pragma unroll
    for (int tt = 0; tt < 2; tt++) {
#pragma unroll
        for (int nt = 0; nt < 4; nt++) {
            int oc = nt * 8 + kq;
            int p2 = nt * 4 + l3;
            float b0 = bias[oc], b1 = bias[oc + 1];
            uint32_t h0 = pack2(fmaxf(acc[tt][nt][0] + b0, 0.f), fmaxf(acc[tt][nt][1] + b1, 0.f));
            uint32_t h1 = pack2(fmaxf(acc[tt][nt][2] + b0, 0.f), fmaxf(acc[tt][nt][3] + b1, 0.f));
            int m = m0 + tt * 128;
            if (MODE == 0) {
                int pl = p0 + m, phh = pl + 8;
                if (pl < BBSZ) out[(size_t)(n_img * 16 + p2) * BBSZ + pl] = h0;
                if (phh < BBSZ) out[(size_t)(n_img * 16 + p2) * BBSZ + phh] = h1;
            } else {
                int oyl = y0t + (m >> 3), oxl = x0t + (m & 7);
                int oyh = y0t + ((m + 8) >> 3), oxh = x0t + ((m + 8) & 7);
                if (oyl < HP) out[((size_t)(n_img * 16 + p2) * HP + oyl) * HP + oxl] = h0;
                if (oyh < HP) out[((size_t)(n_img * 16 + p2) * HP + oyh) * HP + oxh] = h1;
            }
        }
    }
}

// ---------------- WIDE conv4 (256 px / block, 1 oc) ------------------------------
template<int MODE, int OUTM>
__global__ void __launch_bounds__(256)
conv_hmma_n(const uint32_t* __restrict__ in,
            const uint4* __restrict__ wpack,
            float* __restrict__ out) {
    extern __shared__ char smem[];
    uint4* ws = (uint4*)smem;
    constexpr int PSTR = (MODE == 0) ? WP0 : WP1;
    constexpr int WROW = (MODE == 0) ? 35 : 10;
    constexpr int NPOS = (MODE == 0) ? WNP0 : WNP1;
    uint32_t* hhi = (uint32_t*)(smem + WSC_BYTES);

    const int tid = threadIdx.x;
    const int wid = tid >> 5;
    const int lane = tid & 31;
    const int rg = lane >> 2;
    const int l3 = lane & 3;

    int n_img, p0 = 0, y_first = 0, y0t = 0, x0t = 0;
    if (MODE == 0) {
        n_img = blockIdx.x / 5;
        p0 = (blockIdx.x % 5) * 256;
        y_first = p0 / 33;
    } else {
        int b = blockIdx.x;
        int tx = b % 33; b /= 33;
        int ty = b % 9; b /= 9;
        n_img = b; y0t = ty * 32; x0t = tx * 8;
    }

    load_w4c(wpack, ws, tid);

    if (MODE == 0) {
        for (int e = tid; e < 16 * NPOS; e += 256) {
            int pair = e / NPOS, pos = e % NPOS;
            int row = pos / 35, xp = pos % 35;
            int gy = y_first - 1 + row, gx = xp - 1;
            bool ok = (gy >= 0) && (gy < 33) && (xp >= 1) && (xp < 34);
            hhi[pair * PSTR + pos] =
                ok ? in[(size_t)(n_img * 16 + pair) * BBSZ + gy * 33 + gx] : 0u;
        }
    } else {
        for (int e = tid; e < 16 * NPOS; e += 256) {
            int pair = e / NPOS, pos = e % NPOS;
            int row = pos / 10, xp = pos % 10;
            int gy = y0t - 1 + row, gx = x0t - 1 + xp;
            bool ok = (gy >= 0) && (gy < HP) && (gx >= 0) && (gx < HP);
            hhi[pair * PSTR + pos] =
                ok ? in[((size_t)(n_img * 16 + pair) * HP + gy) * HP + gx] : 0u;
        }
    }
    __syncthreads();

    const int m0 = wid * 16 + rg;
    int base[4];
#pragma unroll
    for (int q = 0; q < 4; q++) {
        int m = m0 + (q & 1) * 8 + (q >> 1) * 128;
        if (MODE == 0) {
            int p = p0 + m;
            int yl = p / 33;
            base[q] = (p < BBSZ) ? (yl - y_first) * 35 + (p - yl * 33) : 0;
        } else {
            base[q] = (m >> 3) * 10 + (m & 7);
        }
    }
    const uint32_t* ph = hhi + l3 * PSTR;

    float acc[2][4];
#pragma unroll
    for (int tt = 0; tt < 2; tt++)
#pragma unroll
        for (int i = 0; i < 4; i++) acc[tt][i] = 0.f;

#pragma unroll
    for (int t = 0; t < 9; t++) {
        const int toff = (t / 3) * WROW + (t % 3);
#pragma unroll
        for (int e2 = 0; e2 < 2; e2++) {
            const int c = 2 * t + e2;
            const int pb = e2 * 8 * PSTR + toff;
            uint32_t a0 = ph[base[0] + pb];
            uint32_t a1 = ph[base[1] + pb];
            uint32_t a2 = ph[base[0] + pb + 4 * PSTR];
            uint32_t a3 = ph[base[1] + pb + 4 * PSTR];
            uint32_t a4 = ph[base[2] + pb];
            uint32_t a5 = ph[base[3] + pb];
            uint32_t a6 = ph[base[2] + pb + 4 * PSTR];
            uint32_t a7 = ph[base[3] + pb + 4 * PSTR];
            uint4 B = ws[(c * 4 + l3) * 10 + rg];
            HMMA16816(acc[0], a0, a1, a2, a3, B.x, B.y);
            HMMA16816(acc[0], a0, a1, a2, a3, B.z, B.w);
            HMMA16816(acc[1], a4, a5, a6, a7, B.x, B.y);
            HMMA16816(acc[1], a4, a5, a6, a7, B.z, B.w);
        }
    }

    if (l3 == 0) {
#pragma unroll
        for (int tt = 0; tt < 2; tt++) {
            int m = m0 + tt * 128;
            if (OUTM == 1) {
                int pl = p0 + m, phh = pl + 8;
                if (pl < BBSZ) out[(size_t)pl * NCOL + n_img] = acc[tt][0];
                if (phh < BBSZ) out[(size_t)phh * NCOL + n_img] = acc[tt][2];
            } else {
                int gyl = y0t + (m >> 3), gxl = x0t + (m & 7);
                int gyh = y0t + ((m + 8) >> 3), gxh = x0t + ((m + 8) & 7);
                if (gyl < HP) { int ix = ximg_idx(n_img, gyl, gxl); out[ix] -= acc[tt][0]; }
                if (gyh < HP) { int ix = ximg_idx(n_img, gyh, gxh); out[ix] -= acc[tt][2]; }
            }
        }
    }
}

// ---------------- blockify / unblockify ------------------------------------------
__global__ void blockify_input_kernel(const float* __restrict__ in, float* __restrict__ Xb) {
    int idx = blockIdx.x * blockDim.x + threadIdx.x;
    if (idx >= BBSZ * NCOL) return;
    int r = idx / NCOL, n = idx % NCOL;
    int i = r / BQ, j = r % BQ;
    int l = n / (NH * NS), h = (n / NS) % NH, s = n % NS;
    Xb[idx] = in[(s * HP + h * BQ + i) * HP + l * BQ + j];
}
__global__ void unblockify_kernel(const float* __restrict__ X, float* __restrict__ img) {
    int idx = blockIdx.x * blockDim.x + threadIdx.x;
    if (idx >= IMGPIX) return;
    int s = idx / (HP * HP);
    int rem = idx % (HP * HP);
    int R = rem / HP, C = rem % HP;
    int h = R / BQ, i = R % BQ, l = C / BQ, j = C % BQ;
    img[idx] = X[(i * BQ + j) * NCOL + (l * (NH * NS) + h * NS + s)];
}

// ---------------- host driver ------------------------------------------------------
extern "C" void kernel_launch(void* const* d_in, const int* in_sizes, int n_in,
                              void* d_out, int out_size) {
    const float* inputs = (const float*)d_in[0];
    const float* A      = (const float*)d_in[1];
    const float* Q      = (const float*)d_in[2];
    const float* steps  = (const float*)d_in[3];
    const float* den_w1 = (const float*)d_in[4];
    const float* den_b1 = (const float*)d_in[5];
    const float* den_w2 = (const float*)d_in[6];
    const float* den_b2 = (const float*)d_in[7];
    const float* den_w3 = (const float*)d_in[8];
    const float* den_b3 = (const float*)d_in[9];
    const float* den_w4 = (const float*)d_in[10];
    const float* deb_w1 = (const float*)d_in[11];
    const float* deb_b1 = (const float*)d_in[12];
    const float* deb_w2 = (const float*)d_in[13];
    const float* deb_b2 = (const float*)d_in[14];
    const float* deb_w3 = (const float*)d_in[15];
    const float* deb_b3 = (const float*)d_in[16];
    const float* deb_w4 = (const float*)d_in[17];
    int layers = in_sizes[3];

    float *pX, *pY, *pR, *pZ, *pN, *pAtA;
    uint32_t *pT1, *pT2, *pmA, *pmAT, *pmQ, *pmAtA;
    uint4 *pW4, *pW4c;
    cudaGetSymbolAddress((void**)&pX, g_X);
    cudaGetSymbolAddress((void**)&pY, g_y);
    cudaGetSymbolAddress((void**)&pR, g_r);
    cudaGetSymbolAddress((void**)&pZ, g_z);
    cudaGetSymbolAddress((void**)&pN, g_noise);
    cudaGetSymbolAddress((void**)&pAtA, g_AtA);
    cudaGetSymbolAddress((void**)&pT1, g_t1);
    cudaGetSymbolAddress((void**)&pT2, g_t2);
    cudaGetSymbolAddress((void**)&pW4, g_wpack4);
    cudaGetSymbolAddress((void**)&pW4c, g_wpack4c);
    cudaGetSymbolAddress((void**)&pmA, g_mA);
    cudaGetSymbolAddress((void**)&pmAT, g_mAT);
    cudaGetSymbolAddress((void**)&pmQ, g_mQ);
    cudaGetSymbolAddress((void**)&pmAtA, g_mAtA);

    const int EW = 256;
    const int EG = (IMGPIX + EW - 1) / EW;

    const int SM0W = WSF_BYTES + 16 * WP0 * 4;
    const int SM1W = WSF_BYTES + 16 * WP1 * 4;
    const int SM0C = WSC_BYTES + 16 * WP0 * 4;
    const int SM1C = WSC_BYTES + 16 * WP1 * 4;
    const int SM12_0 = SM0W + ((13 * 37 + 3) & ~3) * 4 + 320 * 4;
    const int SM12_1 = SM1W + ((36 * 12 + 3) & ~3) * 4 + 320 * 4;
    cudaFuncSetAttribute(conv12_hmma<0>, cudaFuncAttributeMaxDynamicSharedMemorySize, SM12_0);
    cudaFuncSetAttribute(conv12_hmma<1>, cudaFuncAttributeMaxDynamicSharedMemorySize, SM12_1);
    cudaFuncSetAttribute(conv_hmma_w<0>, cudaFuncAttributeMaxDynamicSharedMemorySize, SM0W);
    cudaFuncSetAttribute(conv_hmma_w<1>, cudaFuncAttributeMaxDynamicSharedMemorySize, SM1W);
    cudaFuncSetAttribute(conv_hmma_n<0,1>, cudaFuncAttributeMaxDynamicSharedMemorySize, SM0C);
    cudaFuncSetAttribute(conv_hmma_n<1,3>, cudaFuncAttributeMaxDynamicSharedMemorySize, SM1C);

    const int G0W = NCOL * 5;        // 2560
    const int G1W = 8 * 9 * 33;      // 2376

    const int PS_A   = 545 * 272;
    const int PS_ATQ = 136 * 1092;
    const int PS_AtA = 545 * 1092;

    prep_weights4<<<dim3(8, layers), 256>>>(den_w2, den_w3, den_w4,
                                            deb_w2, deb_w3, deb_w4, pW4, pW4c);
    blockify_input_kernel<<<EG, EW>>>(inputs, pZ);
    prep_mat<<<580, 256>>>(A, 1089, 0, 272, 1089, 272, pmA);
    prep_mat<<<580, 256>>>(A, 1089, 1, 1089, 272, 1092, pmAT);
    prep_mat<<<580, 256>>>(Q, 272, 0, 1089, 272, 1092, pmQ);
    hgemm<0><<<dim3(16, 5), 256>>>(pmA, PS_A, 272, pZ, pY, 272, 512, 1089,
                                   nullptr, nullptr, nullptr, 0);
    hgemm<0><<<dim3(16, 18), 256>>>(pmQ, PS_ATQ, 1092, pY, pX, 1089, 512, 272,
                                    nullptr, nullptr, nullptr, 0);
    hgemm<0><<<dim3(35, 18), 256>>>(pmAT, PS_ATQ, 1092, A, pAtA, 1089, 1089, 272,
                                    nullptr, nullptr, nullptr, 0);
    prep_mat<<<2325, 256>>>(pAtA, 1089, 0, 1089, 1089, 1092, pmAtA);

    for (int n = 0; n < layers; n++) {
        const uint4* wf = pW4 + (size_t)(n * 6) * 2304;
        const uint4* wc = pW4c + (size_t)(n * 2) * 576;
        hgemm<1><<<dim3(16, 5), 256>>>(pmA, PS_A, 272, pX, pR, 272, 512, 1089,
                                       pY, nullptr, nullptr, 0);
        hgemm<2><<<dim3(16, 18), 256>>>(pmAT, PS_ATQ, 1092, pR, pZ, 1089, 512, 272,
                                        pX, nullptr, steps, n);
        conv12_hmma<0><<<G0W, 256, SM12_0>>>(pX, den_w1 + (size_t)n * 32 * 9,
                                             den_b1 + n * 32, wf + 0 * 2304,
                                             den_b2 + n * 32, pT1);
        conv_hmma_w<0><<<G0W, 256, SM0W>>>(pT1, wf + 1 * 2304, den_b3 + n * 32, pT2);
        conv_hmma_n<0,1><<<G0W, 256, SM0C>>>(pT2, wc + 0 * 576, pN);
        hgemm<3><<<dim3(16, 18), 256>>>(pmAtA, PS_AtA, 1092, pN, pX, 1089, 512, 1089,
                                        pZ, pN, steps, n);
        conv12_hmma<1><<<G1W, 256, SM12_1>>>(pX, deb_w1 + (size_t)n * 32 * 9,
                                             deb_b1 + n * 32, wf + 3 * 2304,
                                             deb_b2 + n * 32, pT1);
        conv_hmma_w<1><<<G1W, 256, SM1W>>>(pT1, wf + 4 * 2304, deb_b3 + n * 32, pT2);
        conv_hmma_n<1,3><<<G1W, 256, SM1C>>>(pT2, wc + 1 * 576, pX);
    }

    unblockify_kernel<<<EG, EW>>>(pX, (float*)d_out);
}